// round 6
// baseline (speedup 1.0000x reference)
#include <cuda_runtime.h>
#include <math.h>

// ---------------- scratch (device globals: allocation-free rule) ----------------
__device__ float g_h1[64u * 32u * 128u * 128u];   // conv1 out
__device__ float g_h2[64u * 64u * 64u * 64u];     // conv2 out
__device__ float g_h3[64u * 64u * 32u * 32u];     // conv3 out (h)
__device__ float g_z [64u * 64u * 32u * 32u];     // quantized
__device__ float g_d1[64u * 64u * 64u * 64u];     // deconv1 out
__device__ float g_d2[64u * 32u * 128u * 128u];   // deconv2 out
__device__ double g_loss;

// ---------------- conv k=4 s=2 p=1 + ReLU, 2x2 patch x CO_BLK channels ----------------
// 32 accumulators/thread; weights consumed as float4 rows (1 LDS.128 per 8 FMA).
template <int CIN, int COUT, int CO_BLK>
__global__ void __launch_bounds__(128)
conv_k4s2_relu_t(const float* __restrict__ in,
                 const float* __restrict__ w,
                 const float* __restrict__ bias,
                 float* __restrict__ out,
                 int Hin, int Win) {
    const int Hout = Hin >> 1, Wout = Win >> 1;
    const int GX = Wout >> 1, GY = Hout >> 1;
    __shared__ float ws[CO_BLK * CIN * 16];
    __shared__ float bs[CO_BLK];
    const int co0 = blockIdx.y * CO_BLK;
    const int n   = blockIdx.z;

    for (int i = threadIdx.x; i < CO_BLK * CIN * 16; i += blockDim.x)
        ws[i] = w[co0 * CIN * 16 + i];
    if (threadIdx.x < CO_BLK) bs[threadIdx.x] = bias[co0 + threadIdx.x];
    __syncthreads();

    const int g = blockIdx.x * blockDim.x + threadIdx.x;
    if (g >= GX * GY) return;                        // geometry guard
    const int ox0 = (g % GX) * 2;
    const int oy0 = (g / GX) * 2;

    float acc[CO_BLK][2][2];
#pragma unroll
    for (int j = 0; j < CO_BLK; j++) {
        acc[j][0][0] = bs[j]; acc[j][0][1] = bs[j];
        acc[j][1][0] = bs[j]; acc[j][1][1] = bs[j];
    }

    const float* inb = in + (size_t)n * CIN * Hin * Win;
    for (int ci = 0; ci < CIN; ci++) {
        const float* ip = inb + (size_t)ci * Hin * Win;
#pragma unroll
        for (int ry = 0; ry < 6; ry++) {
            const int iy = oy0 * 2 - 1 + ry;
            const bool rok = (unsigned)iy < (unsigned)Hin;
            const float* rp = ip + iy * Win;
            float c[6];
#pragma unroll
            for (int cc = 0; cc < 6; cc++) {
                int ix = ox0 * 2 - 1 + cc;
                c[cc] = (rok && (unsigned)ix < (unsigned)Win) ? __ldg(rp + ix) : 0.f;
            }
#pragma unroll
            for (int s = 0; s < 2; s++) {
                const int ky = ry - 2 * s;
                if (ky < 0 || ky > 3) continue;
#pragma unroll
                for (int j = 0; j < CO_BLK; j++) {
                    float4 w4 = *(const float4*)&ws[(j * CIN + ci) * 16 + ky * 4];
                    float a0 = acc[j][s][0], a1 = acc[j][s][1];
                    a0 = fmaf(c[0], w4.x, a0); a1 = fmaf(c[2], w4.x, a1);
                    a0 = fmaf(c[1], w4.y, a0); a1 = fmaf(c[3], w4.y, a1);
                    a0 = fmaf(c[2], w4.z, a0); a1 = fmaf(c[4], w4.z, a1);
                    a0 = fmaf(c[3], w4.w, a0); a1 = fmaf(c[5], w4.w, a1);
                    acc[j][s][0] = a0; acc[j][s][1] = a1;
                }
            }
        }
    }
#pragma unroll
    for (int j = 0; j < CO_BLK; j++)
#pragma unroll
        for (int s = 0; s < 2; s++) {
            float2 v;
            v.x = fmaxf(acc[j][s][0], 0.f);
            v.y = fmaxf(acc[j][s][1], 0.f);
            *(float2*)&out[(((size_t)n * COUT + co0 + j) * Hout + oy0 + s) * Wout + ox0] = v;
        }
}

// ---------------- deconv (ConvTranspose2d) k=4 s=2 p=1, 2x4 patch x CO_BLK ----------------
// ACT: 0=relu, 1=sigmoid. Weights loaded per (ci,j) as 4 float4s (registers).
template <int CIN, int COUT, int CO_BLK, int ACT>
__global__ void __launch_bounds__(128)
deconv_k4s2_t(const float* __restrict__ in,
              const float* __restrict__ w,
              const float* __restrict__ bias,
              float* __restrict__ out,
              int Hin, int Win) {
    const int Hout = Hin * 2, Wout = Win * 2;
    const int GX = Wout >> 2, GY = Hout >> 1;
    __shared__ float ws[CIN * CO_BLK * 16];
    __shared__ float bs[CO_BLK];
    const int co0 = blockIdx.y * CO_BLK;
    const int n   = blockIdx.z;

    for (int i = threadIdx.x; i < CIN * CO_BLK * 16; i += blockDim.x) {
        int ci = i / (CO_BLK * 16);
        int r  = i - ci * CO_BLK * 16;
        int j  = r >> 4;
        int t  = r & 15;
        ws[i] = w[((size_t)ci * COUT + co0 + j) * 16 + t];
    }
    if (threadIdx.x < CO_BLK) bs[threadIdx.x] = bias[co0 + threadIdx.x];
    __syncthreads();

    const int g = blockIdx.x * blockDim.x + threadIdx.x;
    if (g >= GX * GY) return;                        // geometry guard
    const int ox0 = (g % GX) * 4;
    const int oy0 = (g / GX) * 2;
    const int iyb = (oy0 >> 1) - 1;
    const int ixb = (ox0 >> 1) - 1;

    float acc[CO_BLK][2][4];
#pragma unroll
    for (int j = 0; j < CO_BLK; j++)
#pragma unroll
        for (int s = 0; s < 2; s++)
#pragma unroll
            for (int p = 0; p < 4; p++) acc[j][s][p] = bs[j];

    const float* inb = in + (size_t)n * CIN * Hin * Win;
    for (int ci = 0; ci < CIN; ci++) {
        const float* ip = inb + (size_t)ci * Hin * Win;
        float r4[3][4];
#pragma unroll
        for (int yy = 0; yy < 3; yy++) {
            const int iy = iyb + yy;
            const bool rok = (unsigned)iy < (unsigned)Hin;
#pragma unroll
            for (int xx = 0; xx < 4; xx++) {
                int ix = ixb + xx;
                r4[yy][xx] = (rok && (unsigned)ix < (unsigned)Win)
                                 ? __ldg(ip + iy * Win + ix) : 0.f;
            }
        }
#pragma unroll
        for (int j = 0; j < CO_BLK; j++) {
            float wr[16];
            *(float4*)&wr[0]  = *(const float4*)&ws[(ci * CO_BLK + j) * 16 + 0];
            *(float4*)&wr[4]  = *(const float4*)&ws[(ci * CO_BLK + j) * 16 + 4];
            *(float4*)&wr[8]  = *(const float4*)&ws[(ci * CO_BLK + j) * 16 + 8];
            *(float4*)&wr[12] = *(const float4*)&ws[(ci * CO_BLK + j) * 16 + 12];
#pragma unroll
            for (int s = 0; s < 2; s++) {
                const int ky0 = (s + 1) & 1;
                const int yyA = 1 + ((s + 1) >> 1);
#pragma unroll
                for (int p = 0; p < 4; p++) {
                    const int kx0 = (p + 1) & 1;
                    const int xxA = 1 + ((p + 1) >> 1);
#pragma unroll
                    for (int a = 0; a < 2; a++)
#pragma unroll
                        for (int b = 0; b < 2; b++)
                            acc[j][s][p] = fmaf(r4[yyA - a][xxA - b],
                                                wr[(ky0 + 2 * a) * 4 + kx0 + 2 * b],
                                                acc[j][s][p]);
                }
            }
        }
    }
#pragma unroll
    for (int j = 0; j < CO_BLK; j++)
#pragma unroll
        for (int s = 0; s < 2; s++) {
            float4 v;
            float t0 = acc[j][s][0], t1 = acc[j][s][1], t2 = acc[j][s][2], t3 = acc[j][s][3];
            if (ACT == 0) {
                v.x = fmaxf(t0, 0.f); v.y = fmaxf(t1, 0.f);
                v.z = fmaxf(t2, 0.f); v.w = fmaxf(t3, 0.f);
            } else {
                v.x = 1.f / (1.f + expf(-t0)); v.y = 1.f / (1.f + expf(-t1));
                v.z = 1.f / (1.f + expf(-t2)); v.w = 1.f / (1.f + expf(-t3));
            }
            *(float4*)&out[(((size_t)n * COUT + co0 + j) * Hout + oy0 + s) * Wout + ox0] = v;
        }
}

// ---------------- VQ: nearest codebook entry + gather + MSE loss ----------------
__global__ void vq_kernel(const float* __restrict__ h,
                          const float* __restrict__ cb,
                          float* __restrict__ z) {
    __shared__ float cs[64][65];
    __shared__ float cn[64];
    __shared__ float red[256];
    const int tid = threadIdx.x;
    const int pt  = blockIdx.x * 256 + tid;
    const int n   = pt >> 10;
    const int pix = pt & 1023;

    float x[64];
    const float* hb = h + (size_t)n * 64 * 1024 + pix;
#pragma unroll
    for (int c = 0; c < 64; c++) x[c] = __ldg(hb + c * 1024);

    float best = 3.4e38f;
    int   bidx = 0;
    for (int chunk = 0; chunk < 8; chunk++) {
        __syncthreads();
        for (int i = tid; i < 4096; i += 256)
            cs[i >> 6][i & 63] = cb[chunk * 4096 + i];
        __syncthreads();
        if (tid < 64) {
            float s = 0.f;
#pragma unroll
            for (int d = 0; d < 64; d++) s = fmaf(cs[tid][d], cs[tid][d], s);
            cn[tid] = s;
        }
        __syncthreads();
        for (int k = 0; k < 64; k++) {
            float dot = 0.f;
#pragma unroll
            for (int d = 0; d < 64; d++) dot = fmaf(x[d], cs[k][d], dot);
            float s = cn[k] - 2.f * dot;
            if (s < best) { best = s; bidx = chunk * 64 + k; }
        }
    }

    float lsum = 0.f;
    const float* qp = cb + bidx * 64;
    float* zb = z + (size_t)n * 64 * 1024 + pix;
#pragma unroll
    for (int d = 0; d < 64; d++) {
        float q = __ldg(qp + d);
        zb[d * 1024] = q;
        float df = x[d] - q;
        lsum = fmaf(df, df, lsum);
    }
    red[tid] = lsum;
    __syncthreads();
    for (int s = 128; s > 0; s >>= 1) {
        if (tid < s) red[tid] += red[tid + s];
        __syncthreads();
    }
    if (tid == 0) atomicAdd(&g_loss, (double)red[0]);
}

__global__ void zero_loss_kernel() { g_loss = 0.0; }

__global__ void write_scalars_kernel(float* __restrict__ out, long long off) {
    float v = (float)(g_loss * (1.0 / 4194304.0));
    out[off]     = v;
    out[off + 1] = v;
}

// ---------------- launch ----------------
extern "C" void kernel_launch(void* const* d_in, const int* in_sizes, int n_in,
                              void* d_out, int out_size) {
    const float* x   = (const float*)d_in[0];
    const float* w1  = (const float*)d_in[1];
    const float* b1  = (const float*)d_in[2];
    const float* w2  = (const float*)d_in[3];
    const float* b2  = (const float*)d_in[4];
    const float* w3  = (const float*)d_in[5];
    const float* b3  = (const float*)d_in[6];
    const float* cb  = (const float*)d_in[7];
    const float* dw1 = (const float*)d_in[8];
    const float* db1 = (const float*)d_in[9];
    const float* dw2 = (const float*)d_in[10];
    const float* db2 = (const float*)d_in[11];
    const float* dw3 = (const float*)d_in[12];
    const float* db3 = (const float*)d_in[13];
    float* out = (float*)d_out;

    float *h1, *h2, *h3, *z, *d1b, *d2b;
    cudaGetSymbolAddress((void**)&h1,  g_h1);
    cudaGetSymbolAddress((void**)&h2,  g_h2);
    cudaGetSymbolAddress((void**)&h3,  g_h3);
    cudaGetSymbolAddress((void**)&z,   g_z);
    cudaGetSymbolAddress((void**)&d1b, g_d1);
    cudaGetSymbolAddress((void**)&d2b, g_d2);

    zero_loss_kernel<<<1, 1>>>();

    // encoder: 2x2 patches; groups = (Hout/2)*(Wout/2), blockDim 128
    conv_k4s2_relu_t<3, 32, 8><<<dim3(32, 4, 64), 128>>>(x,  w1, b1, h1, 256, 256); // 4096 grp
    conv_k4s2_relu_t<32, 64, 8><<<dim3(8, 8, 64), 128>>>(h1, w2, b2, h2, 128, 128); // 1024 grp
    conv_k4s2_relu_t<64, 64, 8><<<dim3(2, 8, 64), 128>>>(h2, w3, b3, h3, 64, 64);   // 256 grp

    // vector quantize (+ loss)
    vq_kernel<<<65536 / 256, 256>>>(h3, cb, z);

    // decoder: 2x4 patches; groups = (Hout/2)*(Wout/4)
    deconv_k4s2_t<64, 64, 4, 0><<<dim3(4, 16, 64), 128>>>(z,   dw1, db1, d1b, 32, 32);   // 512 grp
    deconv_k4s2_t<64, 32, 4, 0><<<dim3(16, 8, 64), 128>>>(d1b, dw2, db2, d2b, 64, 64);   // 2048 grp
    deconv_k4s2_t<32, 3, 3, 1><<<dim3(64, 1, 64), 128>>>(d2b, dw3, db3, out, 128, 128);  // 8192 grp

    write_scalars_kernel<<<1, 1>>>(out, (long long)out_size - 2);
}

// round 10
// speedup vs baseline: 1.0286x; 1.0286x over previous
#include <cuda_runtime.h>
#include <cuda_bf16.h>
#include <math.h>
#include <stdint.h>

// ---- scratch ----
__device__ float g_h1[64u*32u*128u*128u];
__device__ float g_h2[64u*64u*64u*64u];
__device__ float g_h3[64u*64u*32u*32u];
__device__ float g_z [64u*64u*32u*32u];
__device__ float g_d1[64u*64u*64u*64u];
__device__ float g_d2[64u*32u*128u*128u];
__device__ double g_loss;
// pre-split bf16 weights (identity layout for conv, per-parity-class for deconv)
__device__ unsigned short g_B2h[64*512],  g_B2l[64*512];
__device__ unsigned short g_B3h[64*1024], g_B3l[64*1024];
__device__ unsigned short g_D1h[4*64*256], g_D1l[4*64*256];
__device__ unsigned short g_D2h[4*32*256], g_D2l[4*32*256];

__device__ __forceinline__ void mma16816(float* d, const uint32_t* a, const uint32_t* b) {
    asm volatile("mma.sync.aligned.m16n8k16.row.col.f32.bf16.bf16.f32 "
        "{%0,%1,%2,%3}, {%4,%5,%6,%7}, {%8,%9}, {%0,%1,%2,%3};"
        : "+f"(d[0]), "+f"(d[1]), "+f"(d[2]), "+f"(d[3])
        : "r"(a[0]), "r"(a[1]), "r"(a[2]), "r"(a[3]), "r"(b[0]), "r"(b[1]));
}

// ---- weight prep ----
__global__ void prep_split(const float* __restrict__ w, unsigned short* __restrict__ hi,
                           unsigned short* __restrict__ lo, int n) {
    int i = blockIdx.x * blockDim.x + threadIdx.x;
    if (i >= n) return;
    float v = w[i];
    __nv_bfloat16 h = __float2bfloat16_rn(v);
    hi[i] = __bfloat16_as_ushort(h);
    lo[i] = __bfloat16_as_ushort(__float2bfloat16_rn(v - __bfloat162float(h)));
}
template <int CIN, int COUT>
__global__ void prep_deconv(const float* __restrict__ dw, unsigned short* __restrict__ hi,
                            unsigned short* __restrict__ lo) {
    int idx = blockIdx.x * blockDim.x + threadIdx.x;
    if (idx >= 4 * COUT * CIN * 4) return;
    int cls = idx / (COUT * CIN * 4);
    int rem = idx - cls * (COUT * CIN * 4);
    int co = rem / (CIN * 4);
    int r2 = rem - co * (CIN * 4);
    int ci = r2 >> 2, a = (r2 >> 1) & 1, b = r2 & 1;
    int py = cls >> 1, px = cls & 1;
    int ky0 = (py + 1) & 1, kx0 = (px + 1) & 1;
    float v = dw[((size_t)ci * COUT + co) * 16 + (ky0 + 2*a)*4 + (kx0 + 2*b)];
    __nv_bfloat16 h = __float2bfloat16_rn(v);
    hi[idx] = __bfloat16_as_ushort(h);
    lo[idx] = __bfloat16_as_ushort(__float2bfloat16_rn(v - __bfloat162float(h)));
}

// ---- split-bf16 mma.sync implicit GEMM conv/deconv, M=128 pixels, N=COUT ----
// MODE 0: conv k4s2p1+relu. MODE 1: deconv k4s2p1+relu (parity class per block).
// Smem: Ah/Al [128][72] bf16, Bh/Bl [COUT][72] bf16 (72-pitch: conflict-free frags).
template <int CIN, int COUT, int MODE, int LOG2W, int HIN, int WIN>
__global__ void __launch_bounds__(128) gemm_mma(
    const float* __restrict__ in, const unsigned short* __restrict__ Bhg,
    const unsigned short* __restrict__ Blg, const float* __restrict__ bias,
    float* __restrict__ out) {
    constexpr int K = CIN * (MODE ? 4 : 16), NC = K / 64, CPG = MODE ? 16 : 4;
    constexpr int HOUT = MODE ? HIN*2 : HIN/2, WOUT = MODE ? WIN*2 : WIN/2;
    constexpr int WT = 1 << LOG2W, TR = 128 >> LOG2W;
    constexpr int NF = COUT / 8;
    extern __shared__ unsigned short sm[];
    unsigned short* Ah = sm;                 // 128*72
    unsigned short* Al = sm + 128*72;
    unsigned short* Bh = sm + 2*128*72;      // COUT*72
    unsigned short* Bl = Bh + COUT*72;
    __shared__ float bias_s[COUT];
    const int tid = threadIdx.x, wid = tid >> 5, lane = tid & 31;
    const int g = lane >> 2, tg = lane & 3;
    const int n = blockIdx.z;

    int tile = blockIdx.x, py = 0, px = 0, offy = 0, offx = 0, cls = 0;
    if (MODE) { cls = tile & 3; tile >>= 2; py = cls>>1; px = cls&1; offy = (py+1)>>1; offx = (px+1)>>1; }
    const int r0 = tile * TR;
    if (tid < COUT) bias_s[tid] = bias[tid];

    float acc[2][NF][4];
#pragma unroll
    for (int mi = 0; mi < 2; mi++)
#pragma unroll
        for (int nf = 0; nf < NF; nf++)
#pragma unroll
            for (int q = 0; q < 4; q++) acc[mi][nf][q] = 0.f;

    for (int c = 0; c < NC; c++) {
        __syncthreads();                      // prior chunk fully consumed
        // A tile: 128 x 64 hi/lo, guarded gmem reads (im2col)
        for (int e = tid; e < 8192; e += 128) {
            const int m = e >> 6, k = e & 63;
            int iy, ix, ci;
            if (!MODE) {
                ci = c*CPG + (k >> 4);
                iy = 2*(r0 + (m >> LOG2W)) - 1 + ((k >> 2) & 3);
                ix = 2*(m & (WT-1)) - 1 + (k & 3);
            } else {
                ci = c*CPG + (k >> 2);
                iy = r0 + (m >> LOG2W) + offy - ((k >> 1) & 1);
                ix = (m & (WT-1)) + offx - (k & 1);
            }
            float v = ((unsigned)iy < (unsigned)HIN && (unsigned)ix < (unsigned)WIN)
                        ? __ldg(&in[(((size_t)n*CIN + ci)*HIN + iy)*WIN + ix]) : 0.f;
            __nv_bfloat16 h = __float2bfloat16_rn(v);
            __nv_bfloat16 l = __float2bfloat16_rn(v - __bfloat162float(h));
            Ah[m*72 + k] = __bfloat16_as_ushort(h);
            Al[m*72 + k] = __bfloat16_as_ushort(l);
        }
        // B tile: COUT x 64 (pre-split)
        for (int e = tid; e < COUT*64; e += 128) {
            const int co = e >> 6, k = e & 63;
            size_t gi = (MODE ? ((size_t)cls*COUT + co) : (size_t)co) * K + c*64 + k;
            Bh[co*72 + k] = Bhg[gi];
            Bl[co*72 + k] = Blg[gi];
        }
        __syncthreads();
#pragma unroll
        for (int ks = 0; ks < 4; ks++) {
            const int kb = ks*16 + tg*2;
            uint32_t afh[2][4], afl[2][4];
#pragma unroll
            for (int mi = 0; mi < 2; mi++) {
                const int row = wid*32 + mi*16 + g;
                afh[mi][0] = *(const uint32_t*)&Ah[row*72 + kb];
                afh[mi][1] = *(const uint32_t*)&Ah[(row+8)*72 + kb];
                afh[mi][2] = *(const uint32_t*)&Ah[row*72 + kb + 8];
                afh[mi][3] = *(const uint32_t*)&Ah[(row+8)*72 + kb + 8];
                afl[mi][0] = *(const uint32_t*)&Al[row*72 + kb];
                afl[mi][1] = *(const uint32_t*)&Al[(row+8)*72 + kb];
                afl[mi][2] = *(const uint32_t*)&Al[row*72 + kb + 8];
                afl[mi][3] = *(const uint32_t*)&Al[(row+8)*72 + kb + 8];
            }
#pragma unroll
            for (int nf = 0; nf < NF; nf++) {
                const int bn = nf*8 + g;
                uint32_t bfh[2], bfl[2];
                bfh[0] = *(const uint32_t*)&Bh[bn*72 + kb];
                bfh[1] = *(const uint32_t*)&Bh[bn*72 + kb + 8];
                bfl[0] = *(const uint32_t*)&Bl[bn*72 + kb];
                bfl[1] = *(const uint32_t*)&Bl[bn*72 + kb + 8];
#pragma unroll
                for (int mi = 0; mi < 2; mi++) {
                    mma16816(acc[mi][nf], afh[mi], bfh);
                    mma16816(acc[mi][nf], afh[mi], bfl);
                    mma16816(acc[mi][nf], afl[mi], bfh);
                }
            }
        }
    }

    // epilogue: bias + relu, direct gmem writes
    const size_t HW = (size_t)HOUT * WOUT;
#pragma unroll
    for (int mi = 0; mi < 2; mi++)
#pragma unroll
        for (int dr = 0; dr < 2; dr++) {
            const int row = wid*32 + mi*16 + g + dr*8;
            const int pr = r0 + (row >> LOG2W), pc = row & (WT-1);
            const int oy = MODE ? 2*pr + py : pr;
            const int ox = MODE ? 2*pc + px : pc;
            float* op = out + ((size_t)n*COUT*HOUT + oy)*WOUT + ox;
#pragma unroll
            for (int nf = 0; nf < NF; nf++) {
                const int ch = nf*8 + tg*2;
                op[(size_t)ch*HW]     = fmaxf(acc[mi][nf][dr*2+0] + bias_s[ch],     0.f);
                op[(size_t)(ch+1)*HW] = fmaxf(acc[mi][nf][dr*2+1] + bias_s[ch+1], 0.f);
            }
        }
}

// ---- fp32 conv (conv1 only: CIN=3) ----
template <int CIN, int COUT, int CO_BLK>
__global__ void __launch_bounds__(128)
conv_k4s2_relu_t(const float* __restrict__ in, const float* __restrict__ w,
                 const float* __restrict__ bias, float* __restrict__ out, int Hin, int Win) {
    const int Hout = Hin >> 1, Wout = Win >> 1;
    const int GX = Wout >> 1, GY = Hout >> 1;
    __shared__ float ws[CO_BLK * CIN * 16];
    __shared__ float bs[CO_BLK];
    const int co0 = blockIdx.y * CO_BLK, n = blockIdx.z;
    for (int i = threadIdx.x; i < CO_BLK*CIN*16; i += blockDim.x) ws[i] = w[co0*CIN*16 + i];
    if (threadIdx.x < CO_BLK) bs[threadIdx.x] = bias[co0 + threadIdx.x];
    __syncthreads();
    const int g = blockIdx.x * blockDim.x + threadIdx.x;
    if (g >= GX * GY) return;
    const int ox0 = (g % GX) * 2, oy0 = (g / GX) * 2;
    float acc[CO_BLK][2][2];
#pragma unroll
    for (int j = 0; j < CO_BLK; j++) {
        acc[j][0][0]=bs[j]; acc[j][0][1]=bs[j]; acc[j][1][0]=bs[j]; acc[j][1][1]=bs[j];
    }
    const float* inb = in + (size_t)n * CIN * Hin * Win;
    for (int ci = 0; ci < CIN; ci++) {
        const float* ip = inb + (size_t)ci * Hin * Win;
#pragma unroll
        for (int ry = 0; ry < 6; ry++) {
            const int iy = oy0*2 - 1 + ry;
            const bool rok = (unsigned)iy < (unsigned)Hin;
            const float* rp = ip + iy * Win;
            float cc[6];
#pragma unroll
            for (int q = 0; q < 6; q++) {
                int ix = ox0*2 - 1 + q;
                cc[q] = (rok && (unsigned)ix < (unsigned)Win) ? __ldg(rp + ix) : 0.f;
            }
#pragma unroll
            for (int s = 0; s < 2; s++) {
                const int ky = ry - 2*s;
                if (ky < 0 || ky > 3) continue;
#pragma unroll
                for (int j = 0; j < CO_BLK; j++) {
                    float4 w4 = *(const float4*)&ws[(j*CIN + ci)*16 + ky*4];
                    float a0 = acc[j][s][0], a1 = acc[j][s][1];
                    a0 = fmaf(cc[0], w4.x, a0); a1 = fmaf(cc[2], w4.x, a1);
                    a0 = fmaf(cc[1], w4.y, a0); a1 = fmaf(cc[3], w4.y, a1);
                    a0 = fmaf(cc[2], w4.z, a0); a1 = fmaf(cc[4], w4.z, a1);
                    a0 = fmaf(cc[3], w4.w, a0); a1 = fmaf(cc[5], w4.w, a1);
                    acc[j][s][0] = a0; acc[j][s][1] = a1;
                }
            }
        }
    }
#pragma unroll
    for (int j = 0; j < CO_BLK; j++)
#pragma unroll
        for (int s = 0; s < 2; s++) {
            float2 v;
            v.x = fmaxf(acc[j][s][0], 0.f);
            v.y = fmaxf(acc[j][s][1], 0.f);
            *(float2*)&out[(((size_t)n*COUT + co0 + j)*Hout + oy0 + s)*Wout + ox0] = v;
        }
}

// ---- fp32 deconv (deconv3 only, sigmoid) ----
template <int CIN, int COUT, int CO_BLK, int ACT>
__global__ void __launch_bounds__(128)
deconv_k4s2_t(const float* __restrict__ in, const float* __restrict__ w,
              const float* __restrict__ bias, float* __restrict__ out, int Hin, int Win) {
    const int Hout = Hin*2, Wout = Win*2;
    const int GX = Wout >> 2, GY = Hout >> 1;
    __shared__ float ws[CIN * CO_BLK * 16];
    __shared__ float bs[CO_BLK];
    const int co0 = blockIdx.y * CO_BLK, n = blockIdx.z;
    for (int i = threadIdx.x; i < CIN*CO_BLK*16; i += blockDim.x) {
        int ci = i / (CO_BLK*16), r = i - ci*CO_BLK*16, j = r >> 4, t = r & 15;
        ws[i] = w[((size_t)ci*COUT + co0 + j)*16 + t];
    }
    if (threadIdx.x < CO_BLK) bs[threadIdx.x] = bias[co0 + threadIdx.x];
    __syncthreads();
    const int g = blockIdx.x * blockDim.x + threadIdx.x;
    if (g >= GX * GY) return;
    const int ox0 = (g % GX)*4, oy0 = (g / GX)*2;
    const int iyb = (oy0 >> 1) - 1, ixb = (ox0 >> 1) - 1;
    float acc[CO_BLK][2][4];
#pragma unroll
    for (int j = 0; j < CO_BLK; j++)
#pragma unroll
        for (int s = 0; s < 2; s++)
#pragma unroll
            for (int p = 0; p < 4; p++) acc[j][s][p] = bs[j];
    const float* inb = in + (size_t)n * CIN * Hin * Win;
    for (int ci = 0; ci < CIN; ci++) {
        const float* ip = inb + (size_t)ci * Hin * Win;
        float r4[3][4];
#pragma unroll
        for (int yy = 0; yy < 3; yy++) {
            const int iy = iyb + yy;
            const bool rok = (unsigned)iy < (unsigned)Hin;
#pragma unroll
            for (int xx = 0; xx < 4; xx++) {
                int ix = ixb + xx;
                r4[yy][xx] = (rok && (unsigned)ix < (unsigned)Win) ? __ldg(ip + iy*Win + ix) : 0.f;
            }
        }
#pragma unroll
        for (int j = 0; j < CO_BLK; j++) {
            float wr[16];
            *(float4*)&wr[0]  = *(const float4*)&ws[(ci*CO_BLK + j)*16 + 0];
            *(float4*)&wr[4]  = *(const float4*)&ws[(ci*CO_BLK + j)*16 + 4];
            *(float4*)&wr[8]  = *(const float4*)&ws[(ci*CO_BLK + j)*16 + 8];
            *(float4*)&wr[12] = *(const float4*)&ws[(ci*CO_BLK + j)*16 + 12];
#pragma unroll
            for (int s = 0; s < 2; s++) {
                const int ky0 = (s + 1) & 1, yyA = 1 + ((s + 1) >> 1);
#pragma unroll
                for (int p = 0; p < 4; p++) {
                    const int kx0 = (p + 1) & 1, xxA = 1 + ((p + 1) >> 1);
#pragma unroll
                    for (int a = 0; a < 2; a++)
#pragma unroll
                        for (int b = 0; b < 2; b++)
                            acc[j][s][p] = fmaf(r4[yyA - a][xxA - b],
                                                wr[(ky0 + 2*a)*4 + kx0 + 2*b], acc[j][s][p]);
                }
            }
        }
    }
#pragma unroll
    for (int j = 0; j < CO_BLK; j++)
#pragma unroll
        for (int s = 0; s < 2; s++) {
            float4 v;
            float t0 = acc[j][s][0], t1 = acc[j][s][1], t2 = acc[j][s][2], t3 = acc[j][s][3];
            if (ACT == 0) {
                v.x = fmaxf(t0,0.f); v.y = fmaxf(t1,0.f); v.z = fmaxf(t2,0.f); v.w = fmaxf(t3,0.f);
            } else {
                v.x = 1.f/(1.f+expf(-t0)); v.y = 1.f/(1.f+expf(-t1));
                v.z = 1.f/(1.f+expf(-t2)); v.w = 1.f/(1.f+expf(-t3));
            }
            *(float4*)&out[(((size_t)n*COUT + co0 + j)*Hout + oy0 + s)*Wout + ox0] = v;
        }
}

// ---- VQ ----
__global__ void vq_kernel(const float* __restrict__ h, const float* __restrict__ cb,
                          float* __restrict__ z) {
    __shared__ float cs[64][65];
    __shared__ float cn[64];
    __shared__ float red[256];
    const int tid = threadIdx.x;
    const int pt = blockIdx.x * 256 + tid;
    const int n = pt >> 10, pix = pt & 1023;
    float x[64];
    const float* hb = h + (size_t)n*64*1024 + pix;
#pragma unroll
    for (int c = 0; c < 64; c++) x[c] = __ldg(hb + c*1024);
    float best = 3.4e38f;
    int bidx = 0;
    for (int chunk = 0; chunk < 8; chunk++) {
        __syncthreads();
        for (int i = tid; i < 4096; i += 256) cs[i >> 6][i & 63] = cb[chunk*4096 + i];
        __syncthreads();
        if (tid < 64) {
            float s = 0.f;
#pragma unroll
            for (int d = 0; d < 64; d++) s = fmaf(cs[tid][d], cs[tid][d], s);
            cn[tid] = s;
        }
        __syncthreads();
        for (int k = 0; k < 64; k++) {
            float dot = 0.f;
#pragma unroll
            for (int d = 0; d < 64; d++) dot = fmaf(x[d], cs[k][d], dot);
            float s = cn[k] - 2.f*dot;
            if (s < best) { best = s; bidx = chunk*64 + k; }
        }
    }
    float lsum = 0.f;
    const float* qp = cb + bidx*64;
    float* zb = z + (size_t)n*64*1024 + pix;
#pragma unroll
    for (int d = 0; d < 64; d++) {
        float q = __ldg(qp + d);
        zb[d*1024] = q;
        float df = x[d] - q;
        lsum = fmaf(df, df, lsum);
    }
    red[tid] = lsum;
    __syncthreads();
    for (int s = 128; s > 0; s >>= 1) {
        if (tid < s) red[tid] += red[tid + s];
        __syncthreads();
    }
    if (tid == 0) atomicAdd(&g_loss, (double)red[0]);
}

__global__ void zero_loss_kernel() { g_loss = 0.0; }
__global__ void write_scalars_kernel(float* __restrict__ out, long long off) {
    float v = (float)(g_loss * (1.0 / 4194304.0));
    out[off] = v; out[off + 1] = v;
}

// ---- launch ----
extern "C" void kernel_launch(void* const* d_in, const int* in_sizes, int n_in,
                              void* d_out, int out_size) {
    const float* x   = (const float*)d_in[0];
    const float* w1  = (const float*)d_in[1];
    const float* b1  = (const float*)d_in[2];
    const float* w2  = (const float*)d_in[3];
    const float* b2  = (const float*)d_in[4];
    const float* w3  = (const float*)d_in[5];
    const float* b3  = (const float*)d_in[6];
    const float* cb  = (const float*)d_in[7];
    const float* dw1 = (const float*)d_in[8];
    const float* db1 = (const float*)d_in[9];
    const float* dw2 = (const float*)d_in[10];
    const float* db2 = (const float*)d_in[11];
    const float* dw3 = (const float*)d_in[12];
    const float* db3 = (const float*)d_in[13];
    float* out = (float*)d_out;

    float *h1, *h2, *h3, *z, *d1b, *d2b;
    cudaGetSymbolAddress((void**)&h1,  g_h1);
    cudaGetSymbolAddress((void**)&h2,  g_h2);
    cudaGetSymbolAddress((void**)&h3,  g_h3);
    cudaGetSymbolAddress((void**)&z,   g_z);
    cudaGetSymbolAddress((void**)&d1b, g_d1);
    cudaGetSymbolAddress((void**)&d2b, g_d2);
    unsigned short *B2h, *B2l, *B3h, *B3l, *D1h, *D1l, *D2h, *D2l;
    cudaGetSymbolAddress((void**)&B2h, g_B2h); cudaGetSymbolAddress((void**)&B2l, g_B2l);
    cudaGetSymbolAddress((void**)&B3h, g_B3h); cudaGetSymbolAddress((void**)&B3l, g_B3l);
    cudaGetSymbolAddress((void**)&D1h, g_D1h); cudaGetSymbolAddress((void**)&D1l, g_D1l);
    cudaGetSymbolAddress((void**)&D2h, g_D2h); cudaGetSymbolAddress((void**)&D2l, g_D2l);

    // smem: A (2*128*72) + B (2*COUT*72) ushorts
    const int SMEM64 = (2*128*72 + 2*64*72) * 2;   // 55296
    const int SMEM32 = (2*128*72 + 2*32*72) * 2;   // 46080
    cudaFuncSetAttribute(gemm_mma<32,64,0,6,128,128>, cudaFuncAttributeMaxDynamicSharedMemorySize, SMEM64);
    cudaFuncSetAttribute(gemm_mma<64,64,0,5,64,64>,   cudaFuncAttributeMaxDynamicSharedMemorySize, SMEM64);
    cudaFuncSetAttribute(gemm_mma<64,64,1,5,32,32>,   cudaFuncAttributeMaxDynamicSharedMemorySize, SMEM64);
    cudaFuncSetAttribute(gemm_mma<64,32,1,6,64,64>,   cudaFuncAttributeMaxDynamicSharedMemorySize, SMEM32);

    zero_loss_kernel<<<1, 1>>>();

    // weight prep
    prep_split<<<128, 256>>>(w2, B2h, B2l, 64*512);
    prep_split<<<256, 256>>>(w3, B3h, B3l, 64*1024);
    prep_deconv<64, 64><<<256, 256>>>(dw1, D1h, D1l);
    prep_deconv<64, 32><<<128, 256>>>(dw2, D2h, D2l);

    // conv1 fp32
    conv_k4s2_relu_t<3, 32, 8><<<dim3(32, 4, 64), 128>>>(x, w1, b1, h1, 256, 256);
    // conv2/conv3 tensor (mma.sync)
    gemm_mma<32,64,0,6,128,128><<<dim3(32, 1, 64), 128, SMEM64>>>(h1, B2h, B2l, b2, h2);
    gemm_mma<64,64,0,5,64,64>  <<<dim3(8,  1, 64), 128, SMEM64>>>(h2, B3h, B3l, b3, h3);
    // VQ
    vq_kernel<<<65536 / 256, 256>>>(h3, cb, z);
    // deconv1/deconv2 tensor (grid.x = tiles * 4 classes)
    gemm_mma<64,64,1,5,32,32><<<dim3(32,  1, 64), 128, SMEM64>>>(z,   D1h, D1l, db1, d1b);
    gemm_mma<64,32,1,6,64,64><<<dim3(128, 1, 64), 128, SMEM32>>>(d1b, D2h, D2l, db2, d2b);
    // deconv3 fp32 + sigmoid
    deconv_k4s2_t<32, 3, 3, 1><<<dim3(64, 1, 64), 128>>>(d2b, dw3, db3, out, 128, 128);

    write_scalars_kernel<<<1, 1>>>(out, (long long)out_size - 2);
}

// round 13
// speedup vs baseline: 1.0561x; 1.0267x over previous
#include <cuda_runtime.h>
#include <cuda_bf16.h>
#include <math.h>
#include <stdint.h>

// ---- scratch ----
__device__ float g_h1[64u*32u*128u*128u];
__device__ float g_h2[64u*64u*64u*64u];
__device__ float g_h3[64u*64u*32u*32u];
__device__ float g_z [64u*64u*32u*32u];
__device__ float g_d1[64u*64u*64u*64u];
__device__ float g_d2[64u*32u*128u*128u];
__device__ double g_loss;
// pre-split bf16 weights
__device__ unsigned short g_B2h[64*512],  g_B2l[64*512];
__device__ unsigned short g_B3h[64*1024], g_B3l[64*1024];
__device__ unsigned short g_D1h[4*64*256], g_D1l[4*64*256];
__device__ unsigned short g_D2h[4*32*256], g_D2l[4*32*256];

__device__ __forceinline__ void mma16816(float* d, const uint32_t* a, const uint32_t* b) {
    asm volatile("mma.sync.aligned.m16n8k16.row.col.f32.bf16.bf16.f32 "
        "{%0,%1,%2,%3}, {%4,%5,%6,%7}, {%8,%9}, {%0,%1,%2,%3};"
        : "+f"(d[0]), "+f"(d[1]), "+f"(d[2]), "+f"(d[3])
        : "r"(a[0]), "r"(a[1]), "r"(a[2]), "r"(a[3]), "r"(b[0]), "r"(b[1]));
}

__device__ __forceinline__ void bfsplit(float v, unsigned short& h, unsigned short& l) {
    __nv_bfloat16 hb = __float2bfloat16_rn(v);
    h = __bfloat16_as_ushort(hb);
    l = __bfloat16_as_ushort(__float2bfloat16_rn(v - __bfloat162float(hb)));
}

// ---- single merged prep kernel (also zeroes the loss accumulator) ----
__global__ void prep_all(const float* __restrict__ w2, const float* __restrict__ w3,
                         const float* __restrict__ dw1, const float* __restrict__ dw2) {
    int i = blockIdx.x * blockDim.x + threadIdx.x;
    if (i == 0) g_loss = 0.0;
    if (i < 32768) {                                  // conv2: identity layout
        bfsplit(w2[i], g_B2h[i], g_B2l[i]);
    } else if (i < 98304) {                           // conv3
        int j = i - 32768;
        bfsplit(w3[j], g_B3h[j], g_B3l[j]);
    } else if (i < 163840) {                          // deconv1: CIN=64, COUT=64
        int j = i - 98304;
        int cls = j / 16384, rem = j - cls * 16384;
        int co = rem >> 8, r2 = rem & 255;
        int ci = r2 >> 2, a = (r2 >> 1) & 1, b = r2 & 1;
        int ky0 = ((cls >> 1) + 1) & 1, kx0 = ((cls & 1) + 1) & 1;
        bfsplit(dw1[((size_t)ci * 64 + co) * 16 + (ky0 + 2*a)*4 + (kx0 + 2*b)],
                g_D1h[j], g_D1l[j]);
    } else if (i < 196608) {                          // deconv2: CIN=64, COUT=32
        int j = i - 163840;
        int cls = j / 8192, rem = j - cls * 8192;
        int co = rem >> 8, r2 = rem & 255;
        int ci = r2 >> 2, a = (r2 >> 1) & 1, b = r2 & 1;
        int ky0 = ((cls >> 1) + 1) & 1, kx0 = ((cls & 1) + 1) & 1;
        bfsplit(dw2[((size_t)ci * 32 + co) * 16 + (ky0 + 2*a)*4 + (kx0 + 2*b)],
                g_D2h[j], g_D2l[j]);
    }
}

// ---- split-bf16 mma.sync implicit GEMM conv/deconv, M=128 pixels, N=COUT ----
// MODE 0: conv k4s2p1+relu. MODE 1: deconv k4s2p1+relu (parity class per block).
template <int CIN, int COUT, int MODE, int LOG2W, int HIN, int WIN>
__global__ void __launch_bounds__(128) gemm_mma(
    const float* __restrict__ in, const unsigned short* __restrict__ Bhg,
    const unsigned short* __restrict__ Blg, const float* __restrict__ bias,
    float* __restrict__ out) {
    constexpr int K = CIN * (MODE ? 4 : 16), NC = K / 64;
    constexpr int HOUT = MODE ? HIN*2 : HIN/2, WOUT = MODE ? WIN*2 : WIN/2;
    constexpr int WT = 1 << LOG2W, TR = 128 >> LOG2W;
    constexpr int NF = COUT / 8;
    extern __shared__ unsigned short sm[];
    unsigned short* Ah = sm;                 // 128*72
    unsigned short* Al = sm + 128*72;
    unsigned short* Bh = sm + 2*128*72;      // COUT*72
    unsigned short* Bl = Bh + COUT*72;
    __shared__ float bias_s[COUT];
    const int tid = threadIdx.x, wid = tid >> 5, lane = tid & 31;
    const int g = lane >> 2, tg = lane & 3;
    const int n = blockIdx.z;

    int tile = blockIdx.x, py = 0, px = 0, offy = 0, offx = 0, cls = 0;
    if (MODE) { cls = tile & 3; tile >>= 2; py = cls>>1; px = cls&1; offy = (py+1)>>1; offx = (px+1)>>1; }
    const int r0 = tile * TR;
    if (tid < COUT) bias_s[tid] = bias[tid];

    float acc[2][NF][4];
#pragma unroll
    for (int mi = 0; mi < 2; mi++)
#pragma unroll
        for (int nf = 0; nf < NF; nf++)
#pragma unroll
            for (int q = 0; q < 4; q++) acc[mi][nf][q] = 0.f;

    for (int c = 0; c < NC; c++) {
        __syncthreads();                      // prior chunk fully consumed
        // A tile: 128 x 64 hi/lo, 4 k per thread (vectorized)
        for (int e = tid; e < 2048; e += 128) {
            const int m = e >> 4;
            float v0, v1, v2, v3;
            int kdst;
            if (!MODE) {
                const int kv = e & 15, ciL = kv >> 2, ky = kv & 3;
                const int ci = c*4 + ciL;
                const int iy = 2*(r0 + (m >> LOG2W)) - 1 + ky;
                const int ixb = 2*(m & (WT-1)) - 1;
                const bool rok = (unsigned)iy < (unsigned)HIN;
                const float* rp = in + (((size_t)n*CIN + ci)*HIN + iy)*WIN;
                v0 = (rok && (unsigned)(ixb  ) < (unsigned)WIN) ? __ldg(rp + ixb  ) : 0.f;
                v1 = (rok && (unsigned)(ixb+1) < (unsigned)WIN) ? __ldg(rp + ixb+1) : 0.f;
                v2 = (rok && (unsigned)(ixb+2) < (unsigned)WIN) ? __ldg(rp + ixb+2) : 0.f;
                v3 = (rok && (unsigned)(ixb+3) < (unsigned)WIN) ? __ldg(rp + ixb+3) : 0.f;
                kdst = ciL*16 + ky*4;
            } else {
                const int ciL = e & 15;
                const int ci = c*16 + ciL;
                const int iy0 = r0 + (m >> LOG2W) + offy;
                const int ix0 = (m & (WT-1)) + offx;
                const float* ip = in + ((size_t)n*CIN + ci)*HIN*WIN;
                const bool r0k = (unsigned)iy0 < (unsigned)HIN;
                const bool r1k = (unsigned)(iy0-1) < (unsigned)HIN;
                const bool c0k = (unsigned)ix0 < (unsigned)WIN;
                const bool c1k = (unsigned)(ix0-1) < (unsigned)WIN;
                v0 = (r0k && c0k) ? __ldg(ip + iy0*WIN + ix0)       : 0.f;
                v1 = (r0k && c1k) ? __ldg(ip + iy0*WIN + ix0-1)     : 0.f;
                v2 = (r1k && c0k) ? __ldg(ip + (iy0-1)*WIN + ix0)   : 0.f;
                v3 = (r1k && c1k) ? __ldg(ip + (iy0-1)*WIN + ix0-1) : 0.f;
                kdst = ciL*4;
            }
            __nv_bfloat162 h01 = __floats2bfloat162_rn(v0, v1);
            __nv_bfloat162 h23 = __floats2bfloat162_rn(v2, v3);
            __nv_bfloat162 l01 = __floats2bfloat162_rn(v0 - __low2float(h01), v1 - __high2float(h01));
            __nv_bfloat162 l23 = __floats2bfloat162_rn(v2 - __low2float(h23), v3 - __high2float(h23));
            uint2 uh, ul;
            uh.x = *reinterpret_cast<uint32_t*>(&h01);
            uh.y = *reinterpret_cast<uint32_t*>(&h23);
            ul.x = *reinterpret_cast<uint32_t*>(&l01);
            ul.y = *reinterpret_cast<uint32_t*>(&l23);
            *(uint2*)&Ah[m*72 + kdst] = uh;
            *(uint2*)&Al[m*72 + kdst] = ul;
        }
        // B tile: COUT x 64, uint2 copies
        for (int e = tid; e < COUT*16; e += 128) {
            const int co = e >> 4, k4 = (e & 15) * 4;
            size_t gi = (MODE ? ((size_t)cls*COUT + co) : (size_t)co) * K + c*64 + k4;
            *(uint2*)&Bh[co*72 + k4] = *(const uint2*)&Bhg[gi];
            *(uint2*)&Bl[co*72 + k4] = *(const uint2*)&Blg[gi];
        }
        __syncthreads();
#pragma unroll
        for (int ks = 0; ks < 4; ks++) {
            const int kb = ks*16 + tg*2;
            uint32_t afh[2][4], afl[2][4];
#pragma unroll
            for (int mi = 0; mi < 2; mi++) {
                const int row = wid*32 + mi*16 + g;
                afh[mi][0] = *(const uint32_t*)&Ah[row*72 + kb];
                afh[mi][1] = *(const uint32_t*)&Ah[(row+8)*72 + kb];
                afh[mi][2] = *(const uint32_t*)&Ah[row*72 + kb + 8];
                afh[mi][3] = *(const uint32_t*)&Ah[(row+8)*72 + kb + 8];
                afl[mi][0] = *(const uint32_t*)&Al[row*72 + kb];
                afl[mi][1] = *(const uint32_t*)&Al[(row+8)*72 + kb];
                afl[mi][2] = *(const uint32_t*)&Al[row*72 + kb + 8];
                afl[mi][3] = *(const uint32_t*)&Al[(row+8)*72 + kb + 8];
            }
#pragma unroll
            for (int nf = 0; nf < NF; nf++) {
                const int bn = nf*8 + g;
                uint32_t bfh[2], bfl[2];
                bfh[0] = *(const uint32_t*)&Bh[bn*72 + kb];
                bfh[1] = *(const uint32_t*)&Bh[bn*72 + kb + 8];
                bfl[0] = *(const uint32_t*)&Bl[bn*72 + kb];
                bfl[1] = *(const uint32_t*)&Bl[bn*72 + kb + 8];
#pragma unroll
                for (int mi = 0; mi < 2; mi++) {
                    mma16816(acc[mi][nf], afh[mi], bfh);
                    mma16816(acc[mi][nf], afh[mi], bfl);
                    mma16816(acc[mi][nf], afl[mi], bfh);
                }
            }
        }
    }

    // epilogue: bias + relu
    const size_t HW = (size_t)HOUT * WOUT;
#pragma unroll
    for (int mi = 0; mi < 2; mi++)
#pragma unroll
        for (int dr = 0; dr < 2; dr++) {
            const int row = wid*32 + mi*16 + g + dr*8;
            const int pr = r0 + (row >> LOG2W), pc = row & (WT-1);
            const int oy = MODE ? 2*pr + py : pr;
            const int ox = MODE ? 2*pc + px : pc;
            float* op = out + ((size_t)n*COUT*HOUT + oy)*WOUT + ox;
#pragma unroll
            for (int nf = 0; nf < NF; nf++) {
                const int ch = nf*8 + tg*2;
                op[(size_t)ch*HW]     = fmaxf(acc[mi][nf][dr*2+0] + bias_s[ch],     0.f);
                op[(size_t)(ch+1)*HW] = fmaxf(acc[mi][nf][dr*2+1] + bias_s[ch+1], 0.f);
            }
        }
}

// ---- fp32 conv (conv1 only: CIN=3) ----
template <int CIN, int COUT, int CO_BLK>
__global__ void __launch_bounds__(128)
conv_k4s2_relu_t(const float* __restrict__ in, const float* __restrict__ w,
                 const float* __restrict__ bias, float* __restrict__ out, int Hin, int Win) {
    const int Hout = Hin >> 1, Wout = Win >> 1;
    const int GX = Wout >> 1, GY = Hout >> 1;
    __shared__ float ws[CO_BLK * CIN * 16];
    __shared__ float bs[CO_BLK];
    const int co0 = blockIdx.y * CO_BLK, n = blockIdx.z;
    for (int i = threadIdx.x; i < CO_BLK*CIN*16; i += blockDim.x) ws[i] = w[co0*CIN*16 + i];
    if (threadIdx.x < CO_BLK) bs[threadIdx.x] = bias[co0 + threadIdx.x];
    __syncthreads();
    const int g = blockIdx.x * blockDim.x + threadIdx.x;
    if (g >= GX * GY) return;
    const int ox0 = (g % GX) * 2, oy0 = (g / GX) * 2;
    float acc[CO_BLK][2][2];
#pragma unroll
    for (int j = 0; j < CO_BLK; j++) {
        acc[j][0][0]=bs[j]; acc[j][0][1]=bs[j]; acc[j][1][0]=bs[j]; acc[j][1][1]=bs[j];
    }
    const float* inb = in + (size_t)n * CIN * Hin * Win;
    for (int ci = 0; ci < CIN; ci++) {
        const float* ip = inb + (size_t)ci * Hin * Win;
#pragma unroll
        for (int ry = 0; ry < 6; ry++) {
            const int iy = oy0*2 - 1 + ry;
            const bool rok = (unsigned)iy < (unsigned)Hin;
            const float* rp = ip + iy * Win;
            float cc[6];
#pragma unroll
            for (int q = 0; q < 6; q++) {
                int ix = ox0*2 - 1 + q;
                cc[q] = (rok && (unsigned)ix < (unsigned)Win) ? __ldg(rp + ix) : 0.f;
            }
#pragma unroll
            for (int s = 0; s < 2; s++) {
                const int ky = ry - 2*s;
                if (ky < 0 || ky > 3) continue;
#pragma unroll
                for (int j = 0; j < CO_BLK; j++) {
                    float4 w4 = *(const float4*)&ws[(j*CIN + ci)*16 + ky*4];
                    float a0 = acc[j][s][0], a1 = acc[j][s][1];
                    a0 = fmaf(cc[0], w4.x, a0); a1 = fmaf(cc[2], w4.x, a1);
                    a0 = fmaf(cc[1], w4.y, a0); a1 = fmaf(cc[3], w4.y, a1);
                    a0 = fmaf(cc[2], w4.z, a0); a1 = fmaf(cc[4], w4.z, a1);
                    a0 = fmaf(cc[3], w4.w, a0); a1 = fmaf(cc[5], w4.w, a1);
                    acc[j][s][0] = a0; acc[j][s][1] = a1;
                }
            }
        }
    }
#pragma unroll
    for (int j = 0; j < CO_BLK; j++)
#pragma unroll
        for (int s = 0; s < 2; s++) {
            float2 v;
            v.x = fmaxf(acc[j][s][0], 0.f);
            v.y = fmaxf(acc[j][s][1], 0.f);
            *(float2*)&out[(((size_t)n*COUT + co0 + j)*Hout + oy0 + s)*Wout + ox0] = v;
        }
}

// ---- fp32 deconv (deconv3 only, sigmoid) ----
template <int CIN, int COUT, int CO_BLK, int ACT>
__global__ void __launch_bounds__(128)
deconv_k4s2_t(const float* __restrict__ in, const float* __restrict__ w,
              const float* __restrict__ bias, float* __restrict__ out, int Hin, int Win) {
    const int Hout = Hin*2, Wout = Win*2;
    const int GX = Wout >> 2, GY = Hout >> 1;
    __shared__ float ws[CIN * CO_BLK * 16];
    __shared__ float bs[CO_BLK];
    const int co0 = blockIdx.y * CO_BLK, n = blockIdx.z;
    for (int i = threadIdx.x; i < CIN*CO_BLK*16; i += blockDim.x) {
        int ci = i / (CO_BLK*16), r = i - ci*CO_BLK*16, j = r >> 4, t = r & 15;
        ws[i] = w[((size_t)ci*COUT + co0 + j)*16 + t];
    }
    if (threadIdx.x < CO_BLK) bs[threadIdx.x] = bias[co0 + threadIdx.x];
    __syncthreads();
    const int g = blockIdx.x * blockDim.x + threadIdx.x;
    if (g >= GX * GY) return;
    const int ox0 = (g % GX)*4, oy0 = (g / GX)*2;
    const int iyb = (oy0 >> 1) - 1, ixb = (ox0 >> 1) - 1;
    float acc[CO_BLK][2][4];
#pragma unroll
    for (int j = 0; j < CO_BLK; j++)
#pragma unroll
        for (int s = 0; s < 2; s++)
#pragma unroll
            for (int p = 0; p < 4; p++) acc[j][s][p] = bs[j];
    const float* inb = in + (size_t)n * CIN * Hin * Win;
    for (int ci = 0; ci < CIN; ci++) {
        const float* ip = inb + (size_t)ci * Hin * Win;
        float r4[3][4];
#pragma unroll
        for (int yy = 0; yy < 3; yy++) {
            const int iy = iyb + yy;
            const bool rok = (unsigned)iy < (unsigned)Hin;
#pragma unroll
            for (int xx = 0; xx < 4; xx++) {
                int ix = ixb + xx;
                r4[yy][xx] = (rok && (unsigned)ix < (unsigned)Win) ? __ldg(ip + iy*Win + ix) : 0.f;
            }
        }
#pragma unroll
        for (int j = 0; j < CO_BLK; j++) {
            float wr[16];
            *(float4*)&wr[0]  = *(const float4*)&ws[(ci*CO_BLK + j)*16 + 0];
            *(float4*)&wr[4]  = *(const float4*)&ws[(ci*CO_BLK + j)*16 + 4];
            *(float4*)&wr[8]  = *(const float4*)&ws[(ci*CO_BLK + j)*16 + 8];
            *(float4*)&wr[12] = *(const float4*)&ws[(ci*CO_BLK + j)*16 + 12];
#pragma unroll
            for (int s = 0; s < 2; s++) {
                const int ky0 = (s + 1) & 1, yyA = 1 + ((s + 1) >> 1);
#pragma unroll
                for (int p = 0; p < 4; p++) {
                    const int kx0 = (p + 1) & 1, xxA = 1 + ((p + 1) >> 1);
#pragma unroll
                    for (int a = 0; a < 2; a++)
#pragma unroll
                        for (int b = 0; b < 2; b++)
                            acc[j][s][p] = fmaf(r4[yyA - a][xxA - b],
                                                wr[(ky0 + 2*a)*4 + kx0 + 2*b], acc[j][s][p]);
                }
            }
        }
    }
#pragma unroll
    for (int j = 0; j < CO_BLK; j++)
#pragma unroll
        for (int s = 0; s < 2; s++) {
            float4 v;
            float t0 = acc[j][s][0], t1 = acc[j][s][1], t2 = acc[j][s][2], t3 = acc[j][s][3];
            if (ACT == 0) {
                v.x = fmaxf(t0,0.f); v.y = fmaxf(t1,0.f); v.z = fmaxf(t2,0.f); v.w = fmaxf(t3,0.f);
            } else {
                v.x = 1.f/(1.f+expf(-t0)); v.y = 1.f/(1.f+expf(-t1));
                v.z = 1.f/(1.f+expf(-t2)); v.w = 1.f/(1.f+expf(-t3));
            }
            *(float4*)&out[(((size_t)n*COUT + co0 + j)*Hout + oy0 + s)*Wout + ox0] = v;
        }
}

// ---- VQ (float4-vectorized codebook dot) ----
__global__ void vq_kernel(const float* __restrict__ h, const float* __restrict__ cb,
                          float* __restrict__ z) {
    __shared__ float cs[64][68];
    __shared__ float cn[64];
    __shared__ float red[256];
    const int tid = threadIdx.x;
    const int pt = blockIdx.x * 256 + tid;
    const int n = pt >> 10, pix = pt & 1023;
    float x[64];
    const float* hb = h + (size_t)n*64*1024 + pix;
#pragma unroll
    for (int c = 0; c < 64; c++) x[c] = __ldg(hb + c*1024);
    float best = 3.4e38f;
    int bidx = 0;
    for (int chunk = 0; chunk < 8; chunk++) {
        __syncthreads();
        for (int i = tid; i < 1024; i += 256) {
            float4 v = *(const float4*)&cb[chunk*4096 + i*4];
            *(float4*)&cs[i >> 4][(i & 15)*4] = v;
        }
        __syncthreads();
        if (tid < 64) {
            float s = 0.f;
#pragma unroll
            for (int d = 0; d < 64; d++) s = fmaf(cs[tid][d], cs[tid][d], s);
            cn[tid] = s;
        }
        __syncthreads();
        for (int k = 0; k < 64; k++) {
            const float4* cp = (const float4*)&cs[k][0];
            float dot = 0.f;
#pragma unroll
            for (int d4 = 0; d4 < 16; d4++) {
                float4 cv = cp[d4];
                dot = fmaf(x[d4*4+0], cv.x, dot);
                dot = fmaf(x[d4*4+1], cv.y, dot);
                dot = fmaf(x[d4*4+2], cv.z, dot);
                dot = fmaf(x[d4*4+3], cv.w, dot);
            }
            float s = cn[k] - 2.f*dot;
            if (s < best) { best = s; bidx = chunk*64 + k; }
        }
    }
    float lsum = 0.f;
    const float* qp = cb + bidx*64;
    float* zb = z + (size_t)n*64*1024 + pix;
#pragma unroll
    for (int d = 0; d < 64; d++) {
        float q = __ldg(qp + d);
        zb[d*1024] = q;
        float df = x[d] - q;
        lsum = fmaf(df, df, lsum);
    }
    red[tid] = lsum;
    __syncthreads();
    for (int s = 128; s > 0; s >>= 1) {
        if (tid < s) red[tid] += red[tid + s];
        __syncthreads();
    }
    if (tid == 0) atomicAdd(&g_loss, (double)red[0]);
}

__global__ void write_scalars_kernel(float* __restrict__ out, long long off) {
    float v = (float)(g_loss * (1.0 / 4194304.0));
    out[off] = v; out[off + 1] = v;
}

// ---- launch ----
extern "C" void kernel_launch(void* const* d_in, const int* in_sizes, int n_in,
                              void* d_out, int out_size) {
    const float* x   = (const float*)d_in[0];
    const float* w1  = (const float*)d_in[1];
    const float* b1  = (const float*)d_in[2];
    const float* w2  = (const float*)d_in[3];
    const float* b2  = (const float*)d_in[4];
    const float* w3  = (const float*)d_in[5];
    const float* b3  = (const float*)d_in[6];
    const float* cb  = (const float*)d_in[7];
    const float* dw1 = (const float*)d_in[8];
    const float* db1 = (const float*)d_in[9];
    const float* dw2 = (const float*)d_in[10];
    const float* db2 = (const float*)d_in[11];
    const float* dw3 = (const float*)d_in[12];
    const float* db3 = (const float*)d_in[13];
    float* out = (float*)d_out;

    float *h1, *h2, *h3, *z, *d1b, *d2b;
    cudaGetSymbolAddress((void**)&h1,  g_h1);
    cudaGetSymbolAddress((void**)&h2,  g_h2);
    cudaGetSymbolAddress((void**)&h3,  g_h3);
    cudaGetSymbolAddress((void**)&z,   g_z);
    cudaGetSymbolAddress((void**)&d1b, g_d1);
    cudaGetSymbolAddress((void**)&d2b, g_d2);
    unsigned short *B2h, *B2l, *B3h, *B3l, *D1h, *D1l, *D2h, *D2l;
    cudaGetSymbolAddress((void**)&B2h, g_B2h); cudaGetSymbolAddress((void**)&B2l, g_B2l);
    cudaGetSymbolAddress((void**)&B3h, g_B3h); cudaGetSymbolAddress((void**)&B3l, g_B3l);
    cudaGetSymbolAddress((void**)&D1h, g_D1h); cudaGetSymbolAddress((void**)&D1l, g_D1l);
    cudaGetSymbolAddress((void**)&D2h, g_D2h); cudaGetSymbolAddress((void**)&D2l, g_D2l);

    const int SMEM64 = (2*128*72 + 2*64*72) * 2;   // 55296
    const int SMEM32 = (2*128*72 + 2*32*72) * 2;   // 46080
    cudaFuncSetAttribute(gemm_mma<32,64,0,6,128,128>, cudaFuncAttributeMaxDynamicSharedMemorySize, SMEM64);
    cudaFuncSetAttribute(gemm_mma<64,64,0,5,64,64>,   cudaFuncAttributeMaxDynamicSharedMemorySize, SMEM64);
    cudaFuncSetAttribute(gemm_mma<64,64,1,5,32,32>,   cudaFuncAttributeMaxDynamicSharedMemorySize, SMEM64);
    cudaFuncSetAttribute(gemm_mma<64,32,1,6,64,64>,   cudaFuncAttributeMaxDynamicSharedMemorySize, SMEM32);

    prep_all<<<768, 256>>>(w2, w3, dw1, dw2);                                     // launch 0
    conv_k4s2_relu_t<3, 32, 8><<<dim3(32, 4, 64), 128>>>(x, w1, b1, h1, 256, 256); // 1
    gemm_mma<32,64,0,6,128,128><<<dim3(32, 1, 64), 128, SMEM64>>>(h1, B2h, B2l, b2, h2); // 2
    gemm_mma<64,64,0,5,64,64>  <<<dim3(8,  1, 64), 128, SMEM64>>>(h2, B3h, B3l, b3, h3); // 3
    vq_kernel<<<65536 / 256, 256>>>(h3, cb, z);                                    // 4
    gemm_mma<64,64,1,5,32,32><<<dim3(32,  1, 64), 128, SMEM64>>>(z,   D1h, D1l, db1, d1b); // 5
    gemm_mma<64,32,1,6,64,64><<<dim3(128, 1, 64), 128, SMEM32>>>(d1b, D2h, D2l, db2, d2b); // 6
    deconv_k4s2_t<32, 3, 3, 1><<<dim3(64, 1, 64), 128>>>(d2b, dw3, db3, out, 128, 128);    // 7
    write_scalars_kernel<<<1, 1>>>(out, (long long)out_size - 2);                  // 8
}

// round 16
// speedup vs baseline: 1.0612x; 1.0049x over previous
#include <cuda_runtime.h>
#include <cuda_bf16.h>
#include <math.h>
#include <stdint.h>

// ---- scratch ----
__device__ float g_h1[64u*32u*128u*128u];
__device__ float g_h2[64u*64u*64u*64u];
__device__ float g_h3[64u*64u*32u*32u];
__device__ float g_z [64u*64u*32u*32u];
__device__ float g_d1[64u*64u*64u*64u];
__device__ float g_d2[64u*32u*128u*128u];
__device__ double g_loss;
// pre-split bf16 weights
__device__ unsigned short g_B2h[64*512],  g_B2l[64*512];
__device__ unsigned short g_B3h[64*1024], g_B3l[64*1024];
__device__ unsigned short g_D1h[4*64*256], g_D1l[4*64*256];
__device__ unsigned short g_D2h[4*32*256], g_D2l[4*32*256];

__device__ __forceinline__ void mma16816(float* d, const uint32_t* a, const uint32_t* b) {
    asm volatile("mma.sync.aligned.m16n8k16.row.col.f32.bf16.bf16.f32 "
        "{%0,%1,%2,%3}, {%4,%5,%6,%7}, {%8,%9}, {%0,%1,%2,%3};"
        : "+f"(d[0]), "+f"(d[1]), "+f"(d[2]), "+f"(d[3])
        : "r"(a[0]), "r"(a[1]), "r"(a[2]), "r"(a[3]), "r"(b[0]), "r"(b[1]));
}

__device__ __forceinline__ void bfsplit(float v, unsigned short& h, unsigned short& l) {
    __nv_bfloat16 hb = __float2bfloat16_rn(v);
    h = __bfloat16_as_ushort(hb);
    l = __bfloat16_as_ushort(__float2bfloat16_rn(v - __bfloat162float(hb)));
}

// ---- single merged prep kernel (also zeroes the loss accumulator) ----
__global__ void prep_all(const float* __restrict__ w2, const float* __restrict__ w3,
                         const float* __restrict__ dw1, const float* __restrict__ dw2) {
    int i = blockIdx.x * blockDim.x + threadIdx.x;
    if (i == 0) g_loss = 0.0;
    if (i < 32768) {
        bfsplit(w2[i], g_B2h[i], g_B2l[i]);
    } else if (i < 98304) {
        int j = i - 32768;
        bfsplit(w3[j], g_B3h[j], g_B3l[j]);
    } else if (i < 163840) {
        int j = i - 98304;
        int cls = j / 16384, rem = j - cls * 16384;
        int co = rem >> 8, r2 = rem & 255;
        int ci = r2 >> 2, a = (r2 >> 1) & 1, b = r2 & 1;
        int ky0 = ((cls >> 1) + 1) & 1, kx0 = ((cls & 1) + 1) & 1;
        bfsplit(dw1[((size_t)ci * 64 + co) * 16 + (ky0 + 2*a)*4 + (kx0 + 2*b)],
                g_D1h[j], g_D1l[j]);
    } else if (i < 196608) {
        int j = i - 163840;
        int cls = j / 8192, rem = j - cls * 8192;
        int co = rem >> 8, r2 = rem & 255;
        int ci = r2 >> 2, a = (r2 >> 1) & 1, b = r2 & 1;
        int ky0 = ((cls >> 1) + 1) & 1, kx0 = ((cls & 1) + 1) & 1;
        bfsplit(dw2[((size_t)ci * 32 + co) * 16 + (ky0 + 2*a)*4 + (kx0 + 2*b)],
                g_D2h[j], g_D2l[j]);
    }
}

// ---- split-bf16 mma.sync implicit GEMM, M=128 pixels, N=COUT, 256 threads ----
// 8 warps; each warp owns 16 M-rows. MODE 0: conv. MODE 1: deconv (parity class).
template <int CIN, int COUT, int MODE, int LOG2W, int HIN, int WIN>
__global__ void __launch_bounds__(256) gemm_mma(
    const float* __restrict__ in, const unsigned short* __restrict__ Bhg,
    const unsigned short* __restrict__ Blg, const float* __restrict__ bias,
    float* __restrict__ out) {
    constexpr int K = CIN * (MODE ? 4 : 16), NC = K / 64;
    constexpr int HOUT = MODE ? HIN*2 : HIN/2, WOUT = MODE ? WIN*2 : WIN/2;
    constexpr int WT = 1 << LOG2W, TR = 128 >> LOG2W;
    constexpr int NF = COUT / 8;
    extern __shared__ unsigned short sm[];
    unsigned short* Ah = sm;                 // 128*72
    unsigned short* Al = sm + 128*72;
    unsigned short* Bh = sm + 2*128*72;      // COUT*72
    unsigned short* Bl = Bh + COUT*72;
    __shared__ float bias_s[COUT];
    const int tid = threadIdx.x, wid = tid >> 5, lane = tid & 31;
    const int g = lane >> 2, tg = lane & 3;
    const int n = blockIdx.z;

    int tile = blockIdx.x, py = 0, px = 0, offy = 0, offx = 0, cls = 0;
    if (MODE) { cls = tile & 3; tile >>= 2; py = cls>>1; px = cls&1; offy = (py+1)>>1; offx = (px+1)>>1; }
    const int r0 = tile * TR;
    if (tid < COUT) bias_s[tid] = bias[tid];

    float acc[NF][4];
#pragma unroll
    for (int nf = 0; nf < NF; nf++)
#pragma unroll
        for (int q = 0; q < 4; q++) acc[nf][q] = 0.f;

    for (int c = 0; c < NC; c++) {
        __syncthreads();                      // prior chunk fully consumed
        // A tile: 128 x 64 hi/lo, 4 k per thread
        for (int e = tid; e < 2048; e += 256) {
            const int m = e >> 4;
            float v0, v1, v2, v3;
            int kdst;
            if (!MODE) {
                const int kv = e & 15, ciL = kv >> 2, ky = kv & 3;
                const int ci = c*4 + ciL;
                const int iy = 2*(r0 + (m >> LOG2W)) - 1 + ky;
                const int ixb = 2*(m & (WT-1)) - 1;
                const bool rok = (unsigned)iy < (unsigned)HIN;
                const float* rp = in + (((size_t)n*CIN + ci)*HIN + iy)*WIN;
                v0 = (rok && (unsigned)(ixb  ) < (unsigned)WIN) ? __ldg(rp + ixb  ) : 0.f;
                v1 = (rok && (unsigned)(ixb+1) < (unsigned)WIN) ? __ldg(rp + ixb+1) : 0.f;
                v2 = (rok && (unsigned)(ixb+2) < (unsigned)WIN) ? __ldg(rp + ixb+2) : 0.f;
                v3 = (rok && (unsigned)(ixb+3) < (unsigned)WIN) ? __ldg(rp + ixb+3) : 0.f;
                kdst = ciL*16 + ky*4;
            } else {
                const int ciL = e & 15;
                const int ci = c*16 + ciL;
                const int iy0 = r0 + (m >> LOG2W) + offy;
                const int ix0 = (m & (WT-1)) + offx;
                const float* ip = in + ((size_t)n*CIN + ci)*HIN*WIN;
                const bool r0k = (unsigned)iy0 < (unsigned)HIN;
                const bool r1k = (unsigned)(iy0-1) < (unsigned)HIN;
                const bool c0k = (unsigned)ix0 < (unsigned)WIN;
                const bool c1k = (unsigned)(ix0-1) < (unsigned)WIN;
                v0 = (r0k && c0k) ? __ldg(ip + iy0*WIN + ix0)       : 0.f;
                v1 = (r0k && c1k) ? __ldg(ip + iy0*WIN + ix0-1)     : 0.f;
                v2 = (r1k && c0k) ? __ldg(ip + (iy0-1)*WIN + ix0)   : 0.f;
                v3 = (r1k && c1k) ? __ldg(ip + (iy0-1)*WIN + ix0-1) : 0.f;
                kdst = ciL*4;
            }
            __nv_bfloat162 h01 = __floats2bfloat162_rn(v0, v1);
            __nv_bfloat162 h23 = __floats2bfloat162_rn(v2, v3);
            __nv_bfloat162 l01 = __floats2bfloat162_rn(v0 - __low2float(h01), v1 - __high2float(h01));
            __nv_bfloat162 l23 = __floats2bfloat162_rn(v2 - __low2float(h23), v3 - __high2float(h23));
            uint2 uh, ul;
            uh.x = *reinterpret_cast<uint32_t*>(&h01);
            uh.y = *reinterpret_cast<uint32_t*>(&h23);
            ul.x = *reinterpret_cast<uint32_t*>(&l01);
            ul.y = *reinterpret_cast<uint32_t*>(&l23);
            *(uint2*)&Ah[m*72 + kdst] = uh;
            *(uint2*)&Al[m*72 + kdst] = ul;
        }
        // B tile: COUT x 64
        for (int e = tid; e < COUT*16; e += 256) {
            const int co = e >> 4, k4 = (e & 15) * 4;
            size_t gi = (MODE ? ((size_t)cls*COUT + co) : (size_t)co) * K + c*64 + k4;
            *(uint2*)&Bh[co*72 + k4] = *(const uint2*)&Bhg[gi];
            *(uint2*)&Bl[co*72 + k4] = *(const uint2*)&Blg[gi];
        }
        __syncthreads();
#pragma unroll
        for (int ks = 0; ks < 4; ks++) {
            const int kb = ks*16 + tg*2;
            const int row = wid*16 + g;
            uint32_t afh[4], afl[4];
            afh[0] = *(const uint32_t*)&Ah[row*72 + kb];
            afh[1] = *(const uint32_t*)&Ah[(row+8)*72 + kb];
            afh[2] = *(const uint32_t*)&Ah[row*72 + kb + 8];
            afh[3] = *(const uint32_t*)&Ah[(row+8)*72 + kb + 8];
            afl[0] = *(const uint32_t*)&Al[row*72 + kb];
            afl[1] = *(const uint32_t*)&Al[(row+8)*72 + kb];
            afl[2] = *(const uint32_t*)&Al[row*72 + kb + 8];
            afl[3] = *(const uint32_t*)&Al[(row+8)*72 + kb + 8];
#pragma unroll
            for (int nf = 0; nf < NF; nf++) {
                const int bn = nf*8 + g;
                uint32_t bfh[2], bfl[2];
                bfh[0] = *(const uint32_t*)&Bh[bn*72 + kb];
                bfh[1] = *(const uint32_t*)&Bh[bn*72 + kb + 8];
                bfl[0] = *(const uint32_t*)&Bl[bn*72 + kb];
                bfl[1] = *(const uint32_t*)&Bl[bn*72 + kb + 8];
                mma16816(acc[nf], afh, bfh);
                mma16816(acc[nf], afh, bfl);
                mma16816(acc[nf], afl, bfh);
            }
        }
    }

    // epilogue: bias + relu
    const size_t HW = (size_t)HOUT * WOUT;
#pragma unroll
    for (int dr = 0; dr < 2; dr++) {
        const int row = wid*16 + g + dr*8;
        const int pr = r0 + (row >> LOG2W), pc = row & (WT-1);
        const int oy = MODE ? 2*pr + py : pr;
        const int ox = MODE ? 2*pc + px : pc;
        float* op = out + ((size_t)n*COUT*HOUT + oy)*WOUT + ox;
#pragma unroll
        for (int nf = 0; nf < NF; nf++) {
            const int ch = nf*8 + tg*2;
            op[(size_t)ch*HW]     = fmaxf(acc[nf][dr*2+0] + bias_s[ch],     0.f);
            op[(size_t)(ch+1)*HW] = fmaxf(acc[nf][dr*2+1] + bias_s[ch+1], 0.f);
        }
    }
}

// ---- fp32 conv (conv1 only: CIN=3) ----
template <int CIN, int COUT, int CO_BLK>
__global__ void __launch_bounds__(128)
conv_k4s2_relu_t(const float* __restrict__ in, const float* __restrict__ w,
                 const float* __restrict__ bias, float* __restrict__ out, int Hin, int Win) {
    const int Hout = Hin >> 1, Wout = Win >> 1;
    const int GX = Wout >> 1, GY = Hout >> 1;
    __shared__ float ws[CO_BLK * CIN * 16];
    __shared__ float bs[CO_BLK];
    const int co0 = blockIdx.y * CO_BLK, n = blockIdx.z;
    for (int i = threadIdx.x; i < CO_BLK*CIN*16; i += blockDim.x) ws[i] = w[co0*CIN*16 + i];
    if (threadIdx.x < CO_BLK) bs[threadIdx.x] = bias[co0 + threadIdx.x];
    __syncthreads();
    const int g = blockIdx.x * blockDim.x + threadIdx.x;
    if (g >= GX * GY) return;
    const int ox0 = (g % GX) * 2, oy0 = (g / GX) * 2;
    float acc[CO_BLK][2][2];
#pragma unroll
    for (int j = 0; j < CO_BLK; j++) {
        acc[j][0][0]=bs[j]; acc[j][0][1]=bs[j]; acc[j][1][0]=bs[j]; acc[j][1][1]=bs[j];
    }
    const float* inb = in + (size_t)n * CIN * Hin * Win;
    for (int ci = 0; ci < CIN; ci++) {
        const float* ip = inb + (size_t)ci * Hin * Win;
#pragma unroll
        for (int ry = 0; ry < 6; ry++) {
            const int iy = oy0*2 - 1 + ry;
            const bool rok = (unsigned)iy < (unsigned)Hin;
            const float* rp = ip + iy * Win;
            float cc[6];
#pragma unroll
            for (int q = 0; q < 6; q++) {
                int ix = ox0*2 - 1 + q;
                cc[q] = (rok && (unsigned)ix < (unsigned)Win) ? __ldg(rp + ix) : 0.f;
            }
#pragma unroll
            for (int s = 0; s < 2; s++) {
                const int ky = ry - 2*s;
                if (ky < 0 || ky > 3) continue;
#pragma unroll
                for (int j = 0; j < CO_BLK; j++) {
                    float4 w4 = *(const float4*)&ws[(j*CIN + ci)*16 + ky*4];
                    float a0 = acc[j][s][0], a1 = acc[j][s][1];
                    a0 = fmaf(cc[0], w4.x, a0); a1 = fmaf(cc[2], w4.x, a1);
                    a0 = fmaf(cc[1], w4.y, a0); a1 = fmaf(cc[3], w4.y, a1);
                    a0 = fmaf(cc[2], w4.z, a0); a1 = fmaf(cc[4], w4.z, a1);
                    a0 = fmaf(cc[3], w4.w, a0); a1 = fmaf(cc[5], w4.w, a1);
                    acc[j][s][0] = a0; acc[j][s][1] = a1;
                }
            }
        }
    }
#pragma unroll
    for (int j = 0; j < CO_BLK; j++)
#pragma unroll
        for (int s = 0; s < 2; s++) {
            float2 v;
            v.x = fmaxf(acc[j][s][0], 0.f);
            v.y = fmaxf(acc[j][s][1], 0.f);
            *(float2*)&out[(((size_t)n*COUT + co0 + j)*Hout + oy0 + s)*Wout + ox0] = v;
        }
}

// ---- fp32 deconv (deconv3 only, sigmoid) ----
template <int CIN, int COUT, int CO_BLK, int ACT>
__global__ void __launch_bounds__(128)
deconv_k4s2_t(const float* __restrict__ in, const float* __restrict__ w,
              const float* __restrict__ bias, float* __restrict__ out, int Hin, int Win) {
    const int Hout = Hin*2, Wout = Win*2;
    const int GX = Wout >> 2, GY = Hout >> 1;
    __shared__ float ws[CIN * CO_BLK * 16];
    __shared__ float bs[CO_BLK];
    const int co0 = blockIdx.y * CO_BLK, n = blockIdx.z;
    for (int i = threadIdx.x; i < CIN*CO_BLK*16; i += blockDim.x) {
        int ci = i / (CO_BLK*16), r = i - ci*CO_BLK*16, j = r >> 4, t = r & 15;
        ws[i] = w[((size_t)ci*COUT + co0 + j)*16 + t];
    }
    if (threadIdx.x < CO_BLK) bs[threadIdx.x] = bias[co0 + threadIdx.x];
    __syncthreads();
    const int g = blockIdx.x * blockDim.x + threadIdx.x;
    if (g >= GX * GY) return;
    const int ox0 = (g % GX)*4, oy0 = (g / GX)*2;
    const int iyb = (oy0 >> 1) - 1, ixb = (ox0 >> 1) - 1;
    float acc[CO_BLK][2][4];
#pragma unroll
    for (int j = 0; j < CO_BLK; j++)
#pragma unroll
        for (int s = 0; s < 2; s++)
#pragma unroll
            for (int p = 0; p < 4; p++) acc[j][s][p] = bs[j];
    const float* inb = in + (size_t)n * CIN * Hin * Win;
    for (int ci = 0; ci < CIN; ci++) {
        const float* ip = inb + (size_t)ci * Hin * Win;
        float r4[3][4];
#pragma unroll
        for (int yy = 0; yy < 3; yy++) {
            const int iy = iyb + yy;
            const bool rok = (unsigned)iy < (unsigned)Hin;
#pragma unroll
            for (int xx = 0; xx < 4; xx++) {
                int ix = ixb + xx;
                r4[yy][xx] = (rok && (unsigned)ix < (unsigned)Win) ? __ldg(ip + iy*Win + ix) : 0.f;
            }
        }
#pragma unroll
        for (int j = 0; j < CO_BLK; j++) {
            float wr[16];
            *(float4*)&wr[0]  = *(const float4*)&ws[(ci*CO_BLK + j)*16 + 0];
            *(float4*)&wr[4]  = *(const float4*)&ws[(ci*CO_BLK + j)*16 + 4];
            *(float4*)&wr[8]  = *(const float4*)&ws[(ci*CO_BLK + j)*16 + 8];
            *(float4*)&wr[12] = *(const float4*)&ws[(ci*CO_BLK + j)*16 + 12];
#pragma unroll
            for (int s = 0; s < 2; s++) {
                const int ky0 = (s + 1) & 1, yyA = 1 + ((s + 1) >> 1);
#pragma unroll
                for (int p = 0; p < 4; p++) {
                    const int kx0 = (p + 1) & 1, xxA = 1 + ((p + 1) >> 1);
#pragma unroll
                    for (int a = 0; a < 2; a++)
#pragma unroll
                        for (int b = 0; b < 2; b++)
                            acc[j][s][p] = fmaf(r4[yyA - a][xxA - b],
                                                wr[(ky0 + 2*a)*4 + kx0 + 2*b], acc[j][s][p]);
                }
            }
        }
    }
#pragma unroll
    for (int j = 0; j < CO_BLK; j++)
#pragma unroll
        for (int s = 0; s < 2; s++) {
            float4 v;
            float t0 = acc[j][s][0], t1 = acc[j][s][1], t2 = acc[j][s][2], t3 = acc[j][s][3];
            if (ACT == 0) {
                v.x = fmaxf(t0,0.f); v.y = fmaxf(t1,0.f); v.z = fmaxf(t2,0.f); v.w = fmaxf(t3,0.f);
            } else {
                v.x = 1.f/(1.f+expf(-t0)); v.y = 1.f/(1.f+expf(-t1));
                v.z = 1.f/(1.f+expf(-t2)); v.w = 1.f/(1.f+expf(-t3));
            }
            *(float4*)&out[(((size_t)n*COUT + co0 + j)*Hout + oy0 + s)*Wout + ox0] = v;
        }
}

// ---- VQ (float4-vectorized codebook dot) ----
__global__ void vq_kernel(const float* __restrict__ h, const float* __restrict__ cb,
                          float* __restrict__ z) {
    __shared__ float cs[64][68];
    __shared__ float cn[64];
    __shared__ float red[256];
    const int tid = threadIdx.x;
    const int pt = blockIdx.x * 256 + tid;
    const int n = pt >> 10, pix = pt & 1023;
    float x[64];
    const float* hb = h + (size_t)n*64*1024 + pix;
#pragma unroll
    for (int c = 0; c < 64; c++) x[c] = __ldg(hb + c*1024);
    float best = 3.4e38f;
    int bidx = 0;
    for (int chunk = 0; chunk < 8; chunk++) {
        __syncthreads();
        for (int i = tid; i < 1024; i += 256) {
            float4 v = *(const float4*)&cb[chunk*4096 + i*4];
            *(float4*)&cs[i >> 4][(i & 15)*4] = v;
        }
        __syncthreads();
        if (tid < 64) {
            float s = 0.f;
#pragma unroll
            for (int d = 0; d < 64; d++) s = fmaf(cs[tid][d], cs[tid][d], s);
            cn[tid] = s;
        }
        __syncthreads();
        for (int k = 0; k < 64; k++) {
            const float4* cp = (const float4*)&cs[k][0];
            float dot = 0.f;
#pragma unroll
            for (int d4 = 0; d4 < 16; d4++) {
                float4 cv = cp[d4];
                dot = fmaf(x[d4*4+0], cv.x, dot);
                dot = fmaf(x[d4*4+1], cv.y, dot);
                dot = fmaf(x[d4*4+2], cv.z, dot);
                dot = fmaf(x[d4*4+3], cv.w, dot);
            }
            float s = cn[k] - 2.f*dot;
            if (s < best) { best = s; bidx = chunk*64 + k; }
        }
    }
    float lsum = 0.f;
    const float* qp = cb + bidx*64;
    float* zb = z + (size_t)n*64*1024 + pix;
#pragma unroll
    for (int d = 0; d < 64; d++) {
        float q = __ldg(qp + d);
        zb[d*1024] = q;
        float df = x[d] - q;
        lsum = fmaf(df, df, lsum);
    }
    red[tid] = lsum;
    __syncthreads();
    for (int s = 128; s > 0; s >>= 1) {
        if (tid < s) red[tid] += red[tid + s];
        __syncthreads();
    }
    if (tid == 0) atomicAdd(&g_loss, (double)red[0]);
}

__global__ void write_scalars_kernel(float* __restrict__ out, long long off) {
    float v = (float)(g_loss * (1.0 / 4194304.0));
    out[off] = v; out[off + 1] = v;
}

// ---- launch ----
extern "C" void kernel_launch(void* const* d_in, const int* in_sizes, int n_in,
                              void* d_out, int out_size) {
    const float* x   = (const float*)d_in[0];
    const float* w1  = (const float*)d_in[1];
    const float* b1  = (const float*)d_in[2];
    const float* w2  = (const float*)d_in[3];
    const float* b2  = (const float*)d_in[4];
    const float* w3  = (const float*)d_in[5];
    const float* b3  = (const float*)d_in[6];
    const float* cb  = (const float*)d_in[7];
    const float* dw1 = (const float*)d_in[8];
    const float* db1 = (const float*)d_in[9];
    const float* dw2 = (const float*)d_in[10];
    const float* db2 = (const float*)d_in[11];
    const float* dw3 = (const float*)d_in[12];
    const float* db3 = (const float*)d_in[13];
    float* out = (float*)d_out;

    float *h1, *h2, *h3, *z, *d1b, *d2b;
    cudaGetSymbolAddress((void**)&h1,  g_h1);
    cudaGetSymbolAddress((void**)&h2,  g_h2);
    cudaGetSymbolAddress((void**)&h3,  g_h3);
    cudaGetSymbolAddress((void**)&z,   g_z);
    cudaGetSymbolAddress((void**)&d1b, g_d1);
    cudaGetSymbolAddress((void**)&d2b, g_d2);
    unsigned short *B2h, *B2l, *B3h, *B3l, *D1h, *D1l, *D2h, *D2l;
    cudaGetSymbolAddress((void**)&B2h, g_B2h); cudaGetSymbolAddress((void**)&B2l, g_B2l);
    cudaGetSymbolAddress((void**)&B3h, g_B3h); cudaGetSymbolAddress((void**)&B3l, g_B3l);
    cudaGetSymbolAddress((void**)&D1h, g_D1h); cudaGetSymbolAddress((void**)&D1l, g_D1l);
    cudaGetSymbolAddress((void**)&D2h, g_D2h); cudaGetSymbolAddress((void**)&D2l, g_D2l);

    const int SMEM64 = (2*128*72 + 2*64*72) * 2;   // 55296
    const int SMEM32 = (2*128*72 + 2*32*72) * 2;   // 46080
    cudaFuncSetAttribute(gemm_mma<32,64,0,6,128,128>, cudaFuncAttributeMaxDynamicSharedMemorySize, SMEM64);
    cudaFuncSetAttribute(gemm_mma<64,64,0,5,64,64>,   cudaFuncAttributeMaxDynamicSharedMemorySize, SMEM64);
    cudaFuncSetAttribute(gemm_mma<64,64,1,5,32,32>,   cudaFuncAttributeMaxDynamicSharedMemorySize, SMEM64);
    cudaFuncSetAttribute(gemm_mma<64,32,1,6,64,64>,   cudaFuncAttributeMaxDynamicSharedMemorySize, SMEM32);

    prep_all<<<768, 256>>>(w2, w3, dw1, dw2);
    conv_k4s2_relu_t<3, 32, 8><<<dim3(32, 4, 64), 128>>>(x, w1, b1, h1, 256, 256);
    gemm_mma<32,64,0,6,128,128><<<dim3(32, 1, 64), 256, SMEM64>>>(h1, B2h, B2l, b2, h2);
    gemm_mma<64,64,0,5,64,64>  <<<dim3(8,  1, 64), 256, SMEM64>>>(h2, B3h, B3l, b3, h3);
    vq_kernel<<<65536 / 256, 256>>>(h3, cb, z);
    gemm_mma<64,64,1,5,32,32><<<dim3(32,  1, 64), 256, SMEM64>>>(z,   D1h, D1l, db1, d1b);
    gemm_mma<64,32,1,6,64,64><<<dim3(128, 1, 64), 256, SMEM32>>>(d1b, D2h, D2l, db2, d2b);
    deconv_k4s2_t<32, 3, 3, 1><<<dim3(64, 1, 64), 128>>>(d2b, dw3, db3, out, 128, 128);
    write_scalars_kernel<<<1, 1>>>(out, (long long)out_size - 2);
}

// round 17
// speedup vs baseline: 1.8205x; 1.7154x over previous
#include <cuda_runtime.h>
#include <cuda_bf16.h>
#include <math.h>
#include <stdint.h>

// ---- scratch ----
__device__ float g_h1[64u*32u*128u*128u];
__device__ float g_h2[64u*64u*64u*64u];
__device__ float g_h3[64u*64u*32u*32u];
__device__ float g_z [64u*64u*32u*32u];
__device__ float g_d1[64u*64u*64u*64u];
__device__ float g_d2[64u*32u*128u*128u];
__device__ double g_loss;
// pre-split bf16 weights
__device__ unsigned short g_B2h[64*512],  g_B2l[64*512];
__device__ unsigned short g_B3h[64*1024], g_B3l[64*1024];
__device__ unsigned short g_D1h[4*64*256], g_D1l[4*64*256];
__device__ unsigned short g_D2h[4*32*256], g_D2l[4*32*256];

__device__ __forceinline__ void mma16816(float* d, const uint32_t* a, const uint32_t* b) {
    asm volatile("mma.sync.aligned.m16n8k16.row.col.f32.bf16.bf16.f32 "
        "{%0,%1,%2,%3}, {%4,%5,%6,%7}, {%8,%9}, {%0,%1,%2,%3};"
        : "+f"(d[0]), "+f"(d[1]), "+f"(d[2]), "+f"(d[3])
        : "r"(a[0]), "r"(a[1]), "r"(a[2]), "r"(a[3]), "r"(b[0]), "r"(b[1]));
}

__device__ __forceinline__ void bfsplit(float v, unsigned short& h, unsigned short& l) {
    __nv_bfloat16 hb = __float2bfloat16_rn(v);
    h = __bfloat16_as_ushort(hb);
    l = __bfloat16_as_ushort(__float2bfloat16_rn(v - __bfloat162float(hb)));
}

// ---- single merged prep kernel (also zeroes the loss accumulator) ----
__global__ void prep_all(const float* __restrict__ w2, const float* __restrict__ w3,
                         const float* __restrict__ dw1, const float* __restrict__ dw2) {
    int i = blockIdx.x * blockDim.x + threadIdx.x;
    if (i == 0) g_loss = 0.0;
    if (i < 32768) {
        bfsplit(w2[i], g_B2h[i], g_B2l[i]);
    } else if (i < 98304) {
        int j = i - 32768;
        bfsplit(w3[j], g_B3h[j], g_B3l[j]);
    } else if (i < 163840) {
        int j = i - 98304;
        int cls = j / 16384, rem = j - cls * 16384;
        int co = rem >> 8, r2 = rem & 255;
        int ci = r2 >> 2, a = (r2 >> 1) & 1, b = r2 & 1;
        int ky0 = ((cls >> 1) + 1) & 1, kx0 = ((cls & 1) + 1) & 1;
        bfsplit(dw1[((size_t)ci * 64 + co) * 16 + (ky0 + 2*a)*4 + (kx0 + 2*b)],
                g_D1h[j], g_D1l[j]);
    } else if (i < 196608) {
        int j = i - 163840;
        int cls = j / 8192, rem = j - cls * 8192;
        int co = rem >> 8, r2 = rem & 255;
        int ci = r2 >> 2, a = (r2 >> 1) & 1, b = r2 & 1;
        int ky0 = ((cls >> 1) + 1) & 1, kx0 = ((cls & 1) + 1) & 1;
        bfsplit(dw2[((size_t)ci * 32 + co) * 16 + (ky0 + 2*a)*4 + (kx0 + 2*b)],
                g_D2h[j], g_D2l[j]);
    }
}

// ---- split-bf16 mma.sync implicit GEMM, M=128 pixels, N=COUT, 256 threads ----
// Coalesced raw staging + im2col fused into fragment construction (no A smem tile).
// MODE 0: conv k4s2p1+relu. MODE 1: deconv k4s2p1+relu (parity class per block).
template <int CIN, int COUT, int MODE, int LOG2W, int HIN, int WIN>
__global__ void __launch_bounds__(256) gemm_mma(
    const float* __restrict__ in, const unsigned short* __restrict__ Bhg,
    const unsigned short* __restrict__ Blg, const float* __restrict__ bias,
    float* __restrict__ out) {
    constexpr int K = CIN * (MODE ? 4 : 16), NC = K / 64, CPG = MODE ? 16 : 4;
    constexpr int HOUT = MODE ? HIN*2 : HIN/2, WOUT = MODE ? WIN*2 : WIN/2;
    constexpr int WT = 1 << LOG2W, TR = 128 >> LOG2W;
    constexpr int NF = COUT / 8;
    constexpr int ROWS = MODE ? (TR + 1) : (2*TR + 2);
    constexpr int RAWF = CPG * ROWS * WIN;          // floats in raw staging
    extern __shared__ float smf[];
    float* raw = smf;                                // RAWF floats
    unsigned short* Bh = (unsigned short*)(smf + RAWF);   // COUT*72
    unsigned short* Bl = Bh + COUT*72;
    __shared__ float bias_s[COUT];
    const int tid = threadIdx.x, wid = tid >> 5, lane = tid & 31;
    const int g = lane >> 2, tg = lane & 3;
    const int n = blockIdx.z;

    int tile = blockIdx.x, py = 0, px = 0, offy = 0, offx = 0, cls = 0;
    if (MODE) { cls = tile & 3; tile >>= 2; py = cls>>1; px = cls&1; offy = (py+1)>>1; offx = (px+1)>>1; }
    const int r0 = tile * TR;
    if (tid < COUT) bias_s[tid] = bias[tid];
    const int iy_start = MODE ? (r0 + offy - 1) : (2*r0 - 1);

    float acc[NF][4];
#pragma unroll
    for (int nf = 0; nf < NF; nf++)
#pragma unroll
        for (int q = 0; q < 4; q++) acc[nf][q] = 0.f;

    const int row = wid*16 + g;                      // warp's base M-row

    for (int c = 0; c < NC; c++) {
        __syncthreads();                             // prior chunk fully consumed
        // stage raw input rows (coalesced float4; OOB rows zeroed)
        for (int q = tid; q < RAWF/4; q += 256) {
            const int cl  = q / (ROWS*WIN/4);
            const int rem = q - cl*(ROWS*WIN/4);
            const int ry  = rem / (WIN/4);
            const int x4  = (rem - ry*(WIN/4)) * 4;
            const int iy  = iy_start + ry;
            float4 v = make_float4(0.f, 0.f, 0.f, 0.f);
            if ((unsigned)iy < (unsigned)HIN)
                v = *(const float4*)&in[(((size_t)n*CIN + c*CPG + cl)*HIN + iy)*WIN + x4];
            *(float4*)&raw[(cl*ROWS + ry)*WIN + x4] = v;
        }
        // B tile: COUT x 64
        for (int e = tid; e < COUT*16; e += 256) {
            const int co = e >> 4, k4 = (e & 15) * 4;
            size_t gi = (MODE ? ((size_t)cls*COUT + co) : (size_t)co) * K + c*64 + k4;
            *(uint2*)&Bh[co*72 + k4] = *(const uint2*)&Bhg[gi];
            *(uint2*)&Bl[co*72 + k4] = *(const uint2*)&Blg[gi];
        }
        __syncthreads();
#pragma unroll
        for (int ks = 0; ks < 4; ks++) {
            const int k0 = ks*16 + tg*2;
            uint32_t afh[4], afl[4];
#pragma unroll
            for (int p = 0; p < 4; p++) {            // [0]=(r,k0) [1]=(r+8,k0) [2]=(r,k0+8) [3]=(r+8,k0+8)
                const int r  = row + ((p & 1) ? 8 : 0);
                const int kk = k0  + ((p >> 1) ? 8 : 0);
                float v0, v1;
                if (!MODE) {
                    const int ciL = kk >> 4, ky = (kk >> 2) & 3, kx = kk & 3;
                    const int ry = 2*(r >> LOG2W) + ky;
                    const int ix = 2*(r & (WT-1)) - 1 + kx;
                    const float* rp = &raw[(ciL*ROWS + ry)*WIN];
                    v0 = ((unsigned)ix     < (unsigned)WIN) ? rp[ix]   : 0.f;
                    v1 = ((unsigned)(ix+1) < (unsigned)WIN) ? rp[ix+1] : 0.f;
                } else {
                    const int ciL = kk >> 2, a = (kk >> 1) & 1;   // kk,kk+1 share ciL,a; b=0,1
                    const int ry = (r >> LOG2W) + 1 - a;
                    const int ix = (r & (WT-1)) + offx;           // b=0 -> ix, b=1 -> ix-1
                    const float* rp = &raw[(ciL*ROWS + ry)*WIN];
                    v0 = ((unsigned)ix     < (unsigned)WIN) ? rp[ix]   : 0.f;
                    v1 = ((unsigned)(ix-1) < (unsigned)WIN) ? rp[ix-1] : 0.f;
                }
                __nv_bfloat162 h01 = __floats2bfloat162_rn(v0, v1);
                __nv_bfloat162 l01 = __floats2bfloat162_rn(v0 - __low2float(h01),
                                                           v1 - __high2float(h01));
                afh[p] = *reinterpret_cast<uint32_t*>(&h01);
                afl[p] = *reinterpret_cast<uint32_t*>(&l01);
            }
#pragma unroll
            for (int nf = 0; nf < NF; nf++) {
                const int bn = nf*8 + g;
                uint32_t bfh[2], bfl[2];
                bfh[0] = *(const uint32_t*)&Bh[bn*72 + k0];
                bfh[1] = *(const uint32_t*)&Bh[bn*72 + k0 + 8];
                bfl[0] = *(const uint32_t*)&Bl[bn*72 + k0];
                bfl[1] = *(const uint32_t*)&Bl[bn*72 + k0 + 8];
                mma16816(acc[nf], afh, bfh);
                mma16816(acc[nf], afh, bfl);
                mma16816(acc[nf], afl, bfh);
            }
        }
    }

    // epilogue: bias + relu
    const size_t HW = (size_t)HOUT * WOUT;
#pragma unroll
    for (int dr = 0; dr < 2; dr++) {
        const int r = row + dr*8;
        const int pr = r0 + (r >> LOG2W), pc = r & (WT-1);
        const int oy = MODE ? 2*pr + py : pr;
        const int ox = MODE ? 2*pc + px : pc;
        float* op = out + ((size_t)n*COUT*HOUT + oy)*WOUT + ox;
#pragma unroll
        for (int nf = 0; nf < NF; nf++) {
            const int ch = nf*8 + tg*2;
            op[(size_t)ch*HW]     = fmaxf(acc[nf][dr*2+0] + bias_s[ch],     0.f);
            op[(size_t)(ch+1)*HW] = fmaxf(acc[nf][dr*2+1] + bias_s[ch+1], 0.f);
        }
    }
}

// ---- fp32 conv (conv1 only: CIN=3) ----
template <int CIN, int COUT, int CO_BLK>
__global__ void __launch_bounds__(128)
conv_k4s2_relu_t(const float* __restrict__ in, const float* __restrict__ w,
                 const float* __restrict__ bias, float* __restrict__ out, int Hin, int Win) {
    const int Hout = Hin >> 1, Wout = Win >> 1;
    const int GX = Wout >> 1, GY = Hout >> 1;
    __shared__ float ws[CO_BLK * CIN * 16];
    __shared__ float bs[CO_BLK];
    const int co0 = blockIdx.y * CO_BLK, n = blockIdx.z;
    for (int i = threadIdx.x; i < CO_BLK*CIN*16; i += blockDim.x) ws[i] = w[co0*CIN*16 + i];
    if (threadIdx.x < CO_BLK) bs[threadIdx.x] = bias[co0 + threadIdx.x];
    __syncthreads();
    const int g = blockIdx.x * blockDim.x + threadIdx.x;
    if (g >= GX * GY) return;
    const int ox0 = (g % GX) * 2, oy0 = (g / GX) * 2;
    float acc[CO_BLK][2][2];
#pragma unroll
    for (int j = 0; j < CO_BLK; j++) {
        acc[j][0][0]=bs[j]; acc[j][0][1]=bs[j]; acc[j][1][0]=bs[j]; acc[j][1][1]=bs[j];
    }
    const float* inb = in + (size_t)n * CIN * Hin * Win;
    for (int ci = 0; ci < CIN; ci++) {
        const float* ip = inb + (size_t)ci * Hin * Win;
#pragma unroll
        for (int ry = 0; ry < 6; ry++) {
            const int iy = oy0*2 - 1 + ry;
            const bool rok = (unsigned)iy < (unsigned)Hin;
            const float* rp = ip + iy * Win;
            float cc[6];
#pragma unroll
            for (int q = 0; q < 6; q++) {
                int ix = ox0*2 - 1 + q;
                cc[q] = (rok && (unsigned)ix < (unsigned)Win) ? __ldg(rp + ix) : 0.f;
            }
#pragma unroll
            for (int s = 0; s < 2; s++) {
                const int ky = ry - 2*s;
                if (ky < 0 || ky > 3) continue;
#pragma unroll
                for (int j = 0; j < CO_BLK; j++) {
                    float4 w4 = *(const float4*)&ws[(j*CIN + ci)*16 + ky*4];
                    float a0 = acc[j][s][0], a1 = acc[j][s][1];
                    a0 = fmaf(cc[0], w4.x, a0); a1 = fmaf(cc[2], w4.x, a1);
                    a0 = fmaf(cc[1], w4.y, a0); a1 = fmaf(cc[3], w4.y, a1);
                    a0 = fmaf(cc[2], w4.z, a0); a1 = fmaf(cc[4], w4.z, a1);
                    a0 = fmaf(cc[3], w4.w, a0); a1 = fmaf(cc[5], w4.w, a1);
                    acc[j][s][0] = a0; acc[j][s][1] = a1;
                }
            }
        }
    }
#pragma unroll
    for (int j = 0; j < CO_BLK; j++)
#pragma unroll
        for (int s = 0; s < 2; s++) {
            float2 v;
            v.x = fmaxf(acc[j][s][0], 0.f);
            v.y = fmaxf(acc[j][s][1], 0.f);
            *(float2*)&out[(((size_t)n*COUT + co0 + j)*Hout + oy0 + s)*Wout + ox0] = v;
        }
}

// ---- fp32 deconv (deconv3 only, sigmoid) ----
template <int CIN, int COUT, int CO_BLK, int ACT>
__global__ void __launch_bounds__(128)
deconv_k4s2_t(const float* __restrict__ in, const float* __restrict__ w,
              const float* __restrict__ bias, float* __restrict__ out, int Hin, int Win) {
    const int Hout = Hin*2, Wout = Win*2;
    const int GX = Wout >> 2, GY = Hout >> 1;
    __shared__ float ws[CIN * CO_BLK * 16];
    __shared__ float bs[CO_BLK];
    const int co0 = blockIdx.y * CO_BLK, n = blockIdx.z;
    for (int i = threadIdx.x; i < CIN*CO_BLK*16; i += blockDim.x) {
        int ci = i / (CO_BLK*16), r = i - ci*CO_BLK*16, j = r >> 4, t = r & 15;
        ws[i] = w[((size_t)ci*COUT + co0 + j)*16 + t];
    }
    if (threadIdx.x < CO_BLK) bs[threadIdx.x] = bias[co0 + threadIdx.x];
    __syncthreads();
    const int g = blockIdx.x * blockDim.x + threadIdx.x;
    if (g >= GX * GY) return;
    const int ox0 = (g % GX)*4, oy0 = (g / GX)*2;
    const int iyb = (oy0 >> 1) - 1, ixb = (ox0 >> 1) - 1;
    float acc[CO_BLK][2][4];
#pragma unroll
    for (int j = 0; j < CO_BLK; j++)
#pragma unroll
        for (int s = 0; s < 2; s++)
#pragma unroll
            for (int p = 0; p < 4; p++) acc[j][s][p] = bs[j];
    const float* inb = in + (size_t)n * CIN * Hin * Win;
    for (int ci = 0; ci < CIN; ci++) {
        const float* ip = inb + (size_t)ci * Hin * Win;
        float r4[3][4];
#pragma unroll
        for (int yy = 0; yy < 3; yy++) {
            const int iy = iyb + yy;
            const bool rok = (unsigned)iy < (unsigned)Hin;
#pragma unroll
            for (int xx = 0; xx < 4; xx++) {
                int ix = ixb + xx;
                r4[yy][xx] = (rok && (unsigned)ix < (unsigned)Win) ? __ldg(ip + iy*Win + ix) : 0.f;
            }
        }
#pragma unroll
        for (int j = 0; j < CO_BLK; j++) {
            float wr[16];
            *(float4*)&wr[0]  = *(const float4*)&ws[(ci*CO_BLK + j)*16 + 0];
            *(float4*)&wr[4]  = *(const float4*)&ws[(ci*CO_BLK + j)*16 + 4];
            *(float4*)&wr[8]  = *(const float4*)&ws[(ci*CO_BLK + j)*16 + 8];
            *(float4*)&wr[12] = *(const float4*)&ws[(ci*CO_BLK + j)*16 + 12];
#pragma unroll
            for (int s = 0; s < 2; s++) {
                const int ky0 = (s + 1) & 1, yyA = 1 + ((s + 1) >> 1);
#pragma unroll
                for (int p = 0; p < 4; p++) {
                    const int kx0 = (p + 1) & 1, xxA = 1 + ((p + 1) >> 1);
#pragma unroll
                    for (int a = 0; a < 2; a++)
#pragma unroll
                        for (int b = 0; b < 2; b++)
                            acc[j][s][p] = fmaf(r4[yyA - a][xxA - b],
                                                wr[(ky0 + 2*a)*4 + kx0 + 2*b], acc[j][s][p]);
                }
            }
        }
    }
#pragma unroll
    for (int j = 0; j < CO_BLK; j++)
#pragma unroll
        for (int s = 0; s < 2; s++) {
            float4 v;
            float t0 = acc[j][s][0], t1 = acc[j][s][1], t2 = acc[j][s][2], t3 = acc[j][s][3];
            if (ACT == 0) {
                v.x = fmaxf(t0,0.f); v.y = fmaxf(t1,0.f); v.z = fmaxf(t2,0.f); v.w = fmaxf(t3,0.f);
            } else {
                v.x = 1.f/(1.f+expf(-t0)); v.y = 1.f/(1.f+expf(-t1));
                v.z = 1.f/(1.f+expf(-t2)); v.w = 1.f/(1.f+expf(-t3));
            }
            *(float4*)&out[(((size_t)n*COUT + co0 + j)*Hout + oy0 + s)*Wout + ox0] = v;
        }
}

// ---- VQ (float4-vectorized codebook dot) ----
__global__ void vq_kernel(const float* __restrict__ h, const float* __restrict__ cb,
                          float* __restrict__ z) {
    __shared__ float cs[64][68];
    __shared__ float cn[64];
    __shared__ float red[256];
    const int tid = threadIdx.x;
    const int pt = blockIdx.x * 256 + tid;
    const int n = pt >> 10, pix = pt & 1023;
    float x[64];
    const float* hb = h + (size_t)n*64*1024 + pix;
#pragma unroll
    for (int c = 0; c < 64; c++) x[c] = __ldg(hb + c*1024);
    float best = 3.4e38f;
    int bidx = 0;
    for (int chunk = 0; chunk < 8; chunk++) {
        __syncthreads();
        for (int i = tid; i < 1024; i += 256) {
            float4 v = *(const float4*)&cb[chunk*4096 + i*4];
            *(float4*)&cs[i >> 4][(i & 15)*4] = v;
        }
        __syncthreads();
        if (tid < 64) {
            float s = 0.f;
#pragma unroll
            for (int d = 0; d < 64; d++) s = fmaf(cs[tid][d], cs[tid][d], s);
            cn[tid] = s;
        }
        __syncthreads();
        for (int k = 0; k < 64; k++) {
            const float4* cp = (const float4*)&cs[k][0];
            float dot = 0.f;
#pragma unroll
            for (int d4 = 0; d4 < 16; d4++) {
                float4 cv = cp[d4];
                dot = fmaf(x[d4*4+0], cv.x, dot);
                dot = fmaf(x[d4*4+1], cv.y, dot);
                dot = fmaf(x[d4*4+2], cv.z, dot);
                dot = fmaf(x[d4*4+3], cv.w, dot);
            }
            float s = cn[k] - 2.f*dot;
            if (s < best) { best = s; bidx = chunk*64 + k; }
        }
    }
    float lsum = 0.f;
    const float* qp = cb + bidx*64;
    float* zb = z + (size_t)n*64*1024 + pix;
#pragma unroll
    for (int d = 0; d < 64; d++) {
        float q = __ldg(qp + d);
        zb[d*1024] = q;
        float df = x[d] - q;
        lsum = fmaf(df, df, lsum);
    }
    red[tid] = lsum;
    __syncthreads();
    for (int s = 128; s > 0; s >>= 1) {
        if (tid < s) red[tid] += red[tid + s];
        __syncthreads();
    }
    if (tid == 0) atomicAdd(&g_loss, (double)red[0]);
}

__global__ void write_scalars_kernel(float* __restrict__ out, long long off) {
    float v = (float)(g_loss * (1.0 / 4194304.0));
    out[off] = v; out[off + 1] = v;
}

// ---- launch ----
extern "C" void kernel_launch(void* const* d_in, const int* in_sizes, int n_in,
                              void* d_out, int out_size) {
    const float* x   = (const float*)d_in[0];
    const float* w1  = (const float*)d_in[1];
    const float* b1  = (const float*)d_in[2];
    const float* w2  = (const float*)d_in[3];
    const float* b2  = (const float*)d_in[4];
    const float* w3  = (const float*)d_in[5];
    const float* b3  = (const float*)d_in[6];
    const float* cb  = (const float*)d_in[7];
    const float* dw1 = (const float*)d_in[8];
    const float* db1 = (const float*)d_in[9];
    const float* dw2 = (const float*)d_in[10];
    const float* db2 = (const float*)d_in[11];
    const float* dw3 = (const float*)d_in[12];
    const float* db3 = (const float*)d_in[13];
    float* out = (float*)d_out;

    float *h1, *h2, *h3, *z, *d1b, *d2b;
    cudaGetSymbolAddress((void**)&h1,  g_h1);
    cudaGetSymbolAddress((void**)&h2,  g_h2);
    cudaGetSymbolAddress((void**)&h3,  g_h3);
    cudaGetSymbolAddress((void**)&z,   g_z);
    cudaGetSymbolAddress((void**)&d1b, g_d1);
    cudaGetSymbolAddress((void**)&d2b, g_d2);
    unsigned short *B2h, *B2l, *B3h, *B3l, *D1h, *D1l, *D2h, *D2l;
    cudaGetSymbolAddress((void**)&B2h, g_B2h); cudaGetSymbolAddress((void**)&B2l, g_B2l);
    cudaGetSymbolAddress((void**)&B3h, g_B3h); cudaGetSymbolAddress((void**)&B3l, g_B3l);
    cudaGetSymbolAddress((void**)&D1h, g_D1h); cudaGetSymbolAddress((void**)&D1l, g_D1l);
    cudaGetSymbolAddress((void**)&D2h, g_D2h); cudaGetSymbolAddress((void**)&D2l, g_D2l);

    // smem per layer: raw floats + 2 * COUT*72 ushorts
    const int S_C2 = 3072*4 + 2*64*72*2;   // 30720
    const int S_C3 = 2560*4 + 2*64*72*2;   // 28672
    const int S_D1 = 2560*4 + 2*64*72*2;   // 28672
    const int S_D2 = 3072*4 + 2*32*72*2;   // 21504

    prep_all<<<768, 256>>>(w2, w3, dw1, dw2);
    conv_k4s2_relu_t<3, 32, 8><<<dim3(32, 4, 64), 128>>>(x, w1, b1, h1, 256, 256);
    gemm_mma<32,64,0,6,128,128><<<dim3(32, 1, 64), 256, S_C2>>>(h1, B2h, B2l, b2, h2);
    gemm_mma<64,64,0,5,64,64>  <<<dim3(8,  1, 64), 256, S_C3>>>(h2, B3h, B3l, b3, h3);
    vq_kernel<<<65536 / 256, 256>>>(h3, cb, z);
    gemm_mma<64,64,1,5,32,32><<<dim3(32,  1, 64), 256, S_D1>>>(z,   D1h, D1l, db1, d1b);
    gemm_mma<64,32,1,6,64,64><<<dim3(128, 1, 64), 256, S_D2>>>(d1b, D2h, D2l, db2, d2b);
    deconv_k4s2_t<32, 3, 3, 1><<<dim3(64, 1, 64), 128>>>(d2b, dw3, db3, out, 128, 128);
    write_scalars_kernel<<<1, 1>>>(out, (long long)out_size - 2);
}